// round 5
// baseline (speedup 1.0000x reference)
#include <cuda_runtime.h>
#include <cuda_bf16.h>
#include <cstdint>
#include <cstddef>

#define E_EDGES 320000
#define N_NODES 20000
#define N_RBF   20
#define TILE_E  128
#define NTILES  2500
#define OUT_S_OFF ((size_t)N_NODES * 3 * 128)
#define PITCH   136     // bf16/row for A & Wphi-B tiles (conflict-free frags)
#define WPITCH  40      // bf16/row for rbf & Ww tiles (K padded to 32)

typedef unsigned long long ull;

// ---- device scratch ----
__device__ float  g_msg[(size_t)E_EDGES * 384];
__device__ int    g_hist[N_NODES];
__device__ int    g_cursor[N_NODES];
__device__ int    g_off[N_NODES + 1];
__device__ int    g_elist[E_EDGES];
__device__ double g_sumsq;

// ---- f32x2 helpers ----
__device__ __forceinline__ ull pack2(float lo, float hi) {
    ull r; asm("mov.b64 %0, {%1,%2};" : "=l"(r) : "f"(lo), "f"(hi)); return r;
}
__device__ __forceinline__ ull mul2(ull a, ull b) {
    ull d; asm("mul.rn.f32x2 %0, %1, %2;" : "=l"(d) : "l"(a), "l"(b)); return d;
}
__device__ __forceinline__ ull add2(ull a, ull b) {
    ull d; asm("add.rn.f32x2 %0, %1, %2;" : "=l"(d) : "l"(a), "l"(b)); return d;
}

// ---- mma.sync m16n8k16 bf16 ----
__device__ __forceinline__ void mma_bf16(float* d, uint32_t a0, uint32_t a1,
                                         uint32_t a2, uint32_t a3,
                                         uint32_t b0, uint32_t b1) {
    asm volatile(
        "mma.sync.aligned.m16n8k16.row.col.f32.bf16.bf16.f32 "
        "{%0,%1,%2,%3}, {%4,%5,%6,%7}, {%8,%9}, {%0,%1,%2,%3};"
        : "+f"(d[0]), "+f"(d[1]), "+f"(d[2]), "+f"(d[3])
        : "r"(a0), "r"(a1), "r"(a2), "r"(a3), "r"(b0), "r"(b1));
}

__device__ __forceinline__ void split1(float x, __nv_bfloat16& h, __nv_bfloat16& l) {
    h = __float2bfloat16(x);
    l = __float2bfloat16(x - __bfloat162float(h));
}
__device__ __forceinline__ void split2(float x0, float x1, uint32_t& hi, uint32_t& lo) {
    __nv_bfloat162 h = __floats2bfloat162_rn(x0, x1);
    float h0 = __low2float(h), h1 = __high2float(h);
    __nv_bfloat162 l = __floats2bfloat162_rn(x0 - h0, x1 - h1);
    hi = *reinterpret_cast<uint32_t*>(&h);
    lo = *reinterpret_cast<uint32_t*>(&l);
}

// smem byte offsets
#define OFF_AHI  0                // 128*136*2 = 34816
#define OFF_ALO  34816
#define OFF_BHI  69632
#define OFF_BLO  104448
#define OFF_WWH  139264           // 128*40*2 = 10240
#define OFF_WWL  149504
#define OFF_RBFH 159744
#define OFF_RBFL 169984
#define OFF_BPHI 180224           // fp32 128
#define OFF_BW   180736
#define SMEM_SZ  181248
// sp transpose buffer aliases A region: float[128][132] = 67584 <= 69632

// ---- CSR/misc kernels ----
__global__ void reset_kernel() {
    int i = blockIdx.x * blockDim.x + threadIdx.x;
    if (i == 0) g_sumsq = 0.0;
    int st = gridDim.x * blockDim.x;
    for (int j = i; j < N_NODES; j += st) g_hist[j] = 0;
}
__global__ void hist_sumsq_kernel(const int* __restrict__ idx,
                                  const float* __restrict__ r) {
    int i = blockIdx.x * blockDim.x + threadIdx.x;
    int st = gridDim.x * blockDim.x;
    for (int e = i; e < E_EDGES; e += st) atomicAdd(&g_hist[idx[e]], 1);
    float s = 0.f;
    for (int j = i; j < E_EDGES * 3; j += st) { float x = r[j]; s += x * x; }
    #pragma unroll
    for (int o = 16; o > 0; o >>= 1) s += __shfl_down_sync(0xffffffffu, s, o);
    __shared__ float ws[8];
    if ((threadIdx.x & 31) == 0) ws[threadIdx.x >> 5] = s;
    __syncthreads();
    if (threadIdx.x < 8) {
        float t = ws[threadIdx.x];
        #pragma unroll
        for (int o = 4; o > 0; o >>= 1) t += __shfl_down_sync(0xffu, t, o);
        if (threadIdx.x == 0) atomicAdd(&g_sumsq, (double)t);
    }
}
__global__ void __launch_bounds__(1024) scan_kernel() {
    const int CH = 20;            // 1024*20 = 20480 >= 20000
    __shared__ int wsum[32];
    int t = threadIdx.x, lane = t & 31, w = t >> 5;
    int base = t * CH;
    int h[CH];
    int s = 0;
    #pragma unroll
    for (int i = 0; i < CH; i++) {
        int j = base + i;
        h[i] = (j < N_NODES) ? g_hist[j] : 0;
        s += h[i];
    }
    int ps = s;
    #pragma unroll
    for (int o = 1; o < 32; o <<= 1) {
        int u = __shfl_up_sync(0xffffffffu, ps, o);
        if (lane >= o) ps += u;
    }
    if (lane == 31) wsum[w] = ps;
    __syncthreads();
    if (w == 0) {
        int v = wsum[lane];
        #pragma unroll
        for (int o = 1; o < 32; o <<= 1) {
            int u = __shfl_up_sync(0xffffffffu, v, o);
            if (lane >= o) v += u;
        }
        wsum[lane] = v;
    }
    __syncthreads();
    int run = ps - s + ((w > 0) ? wsum[w - 1] : 0);
    #pragma unroll
    for (int i = 0; i < CH; i++) {
        int j = base + i;
        if (j < N_NODES) { g_off[j] = run; g_cursor[j] = run; run += h[i]; }
    }
    if (t == 1023) g_off[N_NODES] = run;
}
__global__ void fill_kernel(const int* __restrict__ idx) {
    int i = blockIdx.x * blockDim.x + threadIdx.x;
    int st = gridDim.x * blockDim.x;
    for (int e = i; e < E_EDGES; e += st)
        g_elist[atomicAdd(&g_cursor[idx[e]], 1)] = e;
}

// ---- tensor-core GEMM -> g_msg. grid (X, 3) ----
__global__ void __launch_bounds__(512, 1)
gemm_kernel(const float* __restrict__ s, const float* __restrict__ r,
            const float* __restrict__ Wphi, const float* __restrict__ bphi,
            const float* __restrict__ Ww, const float* __restrict__ bw)
{
    extern __shared__ char sm[];
    __nv_bfloat16* A_hi = (__nv_bfloat16*)(sm + OFF_AHI);
    __nv_bfloat16* A_lo = (__nv_bfloat16*)(sm + OFF_ALO);
    __nv_bfloat16* B_hi = (__nv_bfloat16*)(sm + OFF_BHI);
    __nv_bfloat16* B_lo = (__nv_bfloat16*)(sm + OFF_BLO);
    __nv_bfloat16* Wwh  = (__nv_bfloat16*)(sm + OFF_WWH);
    __nv_bfloat16* Wwl  = (__nv_bfloat16*)(sm + OFF_WWL);
    __nv_bfloat16* Rbh  = (__nv_bfloat16*)(sm + OFF_RBFH);
    __nv_bfloat16* Rbl  = (__nv_bfloat16*)(sm + OFF_RBFL);
    float* bphi_s = (float*)(sm + OFF_BPHI);
    float* bw_s   = (float*)(sm + OFF_BW);
    float* sp     = (float*)(sm + OFF_AHI);     // alias, pitch 132

    const int tid  = threadIdx.x;
    const int wid  = tid >> 5;
    const int lane = tid & 31;
    const int g    = lane >> 2;
    const int t4   = lane & 3;
    const int mt   = wid >> 1;
    const int nh   = wid & 1;
    const int group = blockIdx.y;
    const int goff  = group * 128;

    // ---- one-time weights ----
    for (int i = tid; i < 128 * 128; i += 512) {
        int n = i >> 7, k = i & 127;
        __nv_bfloat16 h, l;
        split1(Wphi[k * 384 + goff + n], h, l);
        B_hi[n * PITCH + k] = h;
        B_lo[n * PITCH + k] = l;
    }
    for (int i = tid; i < 128 * 32; i += 512) {
        int n = i >> 5, k = i & 31;
        float x = (k < N_RBF) ? Ww[k * 384 + goff + n] : 0.f;
        __nv_bfloat16 h, l;
        split1(x, h, l);
        Wwh[n * WPITCH + k] = h;
        Wwl[n * WPITCH + k] = l;
    }
    if (tid < 128) { bphi_s[tid] = bphi[goff + tid]; bw_s[tid] = bw[goff + tid]; }
    __syncthreads();

    const int eL  = tid >> 2;
    const int cbL = (tid & 3) * 32;
    const int e0  = mt * 16 + g;
    const int e1  = e0 + 8;

    for (int tile = blockIdx.x; tile < NTILES; tile += gridDim.x) {
        const int ebase = tile * TILE_E;

        // 1) s-tile loads (latency hidden by rbf + w-MMA)
        float4 st4[8];
        {
            const float* p = &s[(size_t)(ebase + eL) * 128 + cbL];
            #pragma unroll
            for (int q = 0; q < 8; q++) st4[q] = __ldg((const float4*)p + q);
        }

        // 2) rbf (hi/lo bf16, K padded to 32)
        for (int i = tid; i < TILE_E * 32; i += 512) {
            int el = i >> 5, n = i & 31;
            float x = 0.f;
            if (n < N_RBF) {
                float rx = __ldg(&r[(ebase + el) * 3]);
                float ry = __ldg(&r[(ebase + el) * 3 + 1]);
                float rz = __ldg(&r[(ebase + el) * 3 + 2]);
                float rn = sqrtf(rx * rx + ry * ry + rz * rz);
                float tt = sinf((float)(n + 1) * (3.14159265358979323846f / 5.0f) * rn) / rn;
                x = (tt <= 5.0f)
                    ? 0.5f * (cosf(3.14159265358979323846f * 0.2f * tt) + 1.0f) : 0.0f;
            }
            __nv_bfloat16 h, l;
            split1(x, h, l);
            Rbh[el * WPITCH + n] = h;
            Rbl[el * WPITCH + n] = l;
        }
        __syncthreads();   // rbf ready; prev sp copy-out done

        // 3) w-GEMM on tensor cores: acc_w = rbf @ Ww (3 terms, K=32)
        float acc_w[8][4];
        #pragma unroll
        for (int j = 0; j < 8; j++)
            acc_w[j][0] = acc_w[j][1] = acc_w[j][2] = acc_w[j][3] = 0.f;
        #pragma unroll
        for (int kk = 0; kk < 2; kk++) {
            const int kb = kk * 16 + t4 * 2;
            uint32_t ah0 = *(uint32_t*)&Rbh[e0 * WPITCH + kb];
            uint32_t ah1 = *(uint32_t*)&Rbh[e1 * WPITCH + kb];
            uint32_t ah2 = *(uint32_t*)&Rbh[e0 * WPITCH + kb + 8];
            uint32_t ah3 = *(uint32_t*)&Rbh[e1 * WPITCH + kb + 8];
            uint32_t al0 = *(uint32_t*)&Rbl[e0 * WPITCH + kb];
            uint32_t al1 = *(uint32_t*)&Rbl[e1 * WPITCH + kb];
            uint32_t al2 = *(uint32_t*)&Rbl[e0 * WPITCH + kb + 8];
            uint32_t al3 = *(uint32_t*)&Rbl[e1 * WPITCH + kb + 8];
            #pragma unroll
            for (int j = 0; j < 8; j++) {
                int nrow = (nh * 64 + j * 8 + g) * WPITCH + kb;
                uint32_t bh0 = *(uint32_t*)&Wwh[nrow];
                uint32_t bh1 = *(uint32_t*)&Wwh[nrow + 8];
                uint32_t bl0 = *(uint32_t*)&Wwl[nrow];
                uint32_t bl1 = *(uint32_t*)&Wwl[nrow + 8];
                mma_bf16(acc_w[j], ah0, ah1, ah2, ah3, bh0, bh1);
                mma_bf16(acc_w[j], ah0, ah1, ah2, ah3, bl0, bl1);
                mma_bf16(acc_w[j], al0, al1, al2, al3, bh0, bh1);
            }
        }

        // 4) convert staged s -> A_hi/A_lo
        #pragma unroll
        for (int b = 0; b < 4; b++) {
            uint4 hi, lo;
            split2(st4[2*b].x,   st4[2*b].y,   hi.x, lo.x);
            split2(st4[2*b].z,   st4[2*b].w,   hi.y, lo.y);
            split2(st4[2*b+1].x, st4[2*b+1].y, hi.z, lo.z);
            split2(st4[2*b+1].z, st4[2*b+1].w, hi.w, lo.w);
            int o = eL * PITCH + cbL + b * 8;
            *(uint4*)&A_hi[o] = hi;
            *(uint4*)&A_lo[o] = lo;
        }
        __syncthreads();

        // 5) main MMA: phi accumulators
        float acc[8][4];
        #pragma unroll
        for (int j = 0; j < 8; j++)
            acc[j][0] = acc[j][1] = acc[j][2] = acc[j][3] = 0.f;
        #pragma unroll 1
        for (int kk = 0; kk < 8; kk++) {
            const int kb = kk * 16 + t4 * 2;
            const int ra = e0 * PITCH + kb;
            const int rb = e1 * PITCH + kb;
            uint32_t ah0 = *(uint32_t*)&A_hi[ra];
            uint32_t ah1 = *(uint32_t*)&A_hi[rb];
            uint32_t ah2 = *(uint32_t*)&A_hi[ra + 8];
            uint32_t ah3 = *(uint32_t*)&A_hi[rb + 8];
            uint32_t al0 = *(uint32_t*)&A_lo[ra];
            uint32_t al1 = *(uint32_t*)&A_lo[rb];
            uint32_t al2 = *(uint32_t*)&A_lo[ra + 8];
            uint32_t al3 = *(uint32_t*)&A_lo[rb + 8];
            #pragma unroll
            for (int j = 0; j < 8; j++) {
                int nrow = (nh * 64 + j * 8 + g) * PITCH + kk * 16 + t4 * 2;
                uint32_t bh0 = *(uint32_t*)&B_hi[nrow];
                uint32_t bh1 = *(uint32_t*)&B_hi[nrow + 8];
                uint32_t bl0 = *(uint32_t*)&B_lo[nrow];
                uint32_t bl1 = *(uint32_t*)&B_lo[nrow + 8];
                mma_bf16(acc[j], ah0, ah1, ah2, ah3, bh0, bh1);
                mma_bf16(acc[j], ah0, ah1, ah2, ah3, bl0, bl1);
                mma_bf16(acc[j], al0, al1, al2, al3, bh0, bh1);
            }
        }
        __syncthreads();   // A reads done before sp overwrite

        // 6) sp = (acc_w + bw) * (acc + bphi) -> smem transpose (pitch 132)
        #pragma unroll
        for (int j = 0; j < 8; j++) {
            int cj = nh * 64 + j * 8 + t4 * 2;
            ull bp  = *(ull*)&bphi_s[cj];
            ull bwj = *(ull*)&bw_s[cj];
            ull w0 = add2(pack2(acc_w[j][0], acc_w[j][1]), bwj);
            ull w1 = add2(pack2(acc_w[j][2], acc_w[j][3]), bwj);
            ull p0 = mul2(w0, add2(pack2(acc[j][0], acc[j][1]), bp));
            ull p1 = mul2(w1, add2(pack2(acc[j][2], acc[j][3]), bp));
            *(ull*)&sp[e0 * 132 + cj] = p0;
            *(ull*)&sp[e1 * 132 + cj] = p1;
        }
        __syncthreads();

        // 7) coalesced copy-out
        #pragma unroll
        for (int kk = 0; kk < 8; kk++) {
            int i = kk * 512 + tid;
            int edge = i >> 5, ch = i & 31;
            float4 val = *(float4*)&sp[edge * 132 + ch * 4];
            *(float4*)&g_msg[(size_t)(ebase + edge) * 384 + goff + ch * 4] = val;
        }
    }
}

// ---- per-node gather, 2x unrolled for MLP ----
__global__ void __launch_bounds__(128)
gather_kernel(const float* __restrict__ r, const float* __restrict__ v,
              float* __restrict__ out)
{
    const int n = blockIdx.x;
    const int f = threadIdx.x;
    const float ginv = (float)(1.0 / sqrt(g_sumsq));
    const int beg = g_off[n], end = g_off[n + 1];

    float a0 = 0.f, a1 = 0.f, a2 = 0.f, as = 0.f;
    int p = beg;
    #pragma unroll 1
    for (; p + 2 <= end; p += 2) {
        const int ea = g_elist[p], eb = g_elist[p + 1];
        const float* ma = &g_msg[(size_t)ea * 384];
        const float* mb = &g_msg[(size_t)eb * 384];
        const float* va = &v[(size_t)ea * 384];
        const float* vb = &v[(size_t)eb * 384];
        float s0a = ma[f], s1a = ma[128 + f], s2a = ma[256 + f];
        float s0b = mb[f], s1b = mb[128 + f], s2b = mb[256 + f];
        float va0 = va[f], va1 = va[128 + f], va2 = va[256 + f];
        float vb0 = vb[f], vb1 = vb[128 + f], vb2 = vb[256 + f];
        float ra0 = __ldg(&r[ea * 3]), ra1 = __ldg(&r[ea * 3 + 1]), ra2 = __ldg(&r[ea * 3 + 2]);
        float rb0 = __ldg(&r[eb * 3]), rb1 = __ldg(&r[eb * 3 + 1]), rb2 = __ldg(&r[eb * 3 + 2]);
        a0 += s2a * (ra0 * ginv) + s0a * va0 + s2b * (rb0 * ginv) + s0b * vb0;
        a1 += s2a * (ra1 * ginv) + s0a * va1 + s2b * (rb1 * ginv) + s0b * vb1;
        a2 += s2a * (ra2 * ginv) + s0a * va2 + s2b * (rb2 * ginv) + s0b * vb2;
        as += s1a + s1b;
    }
    if (p < end) {
        const int e = g_elist[p];
        const float* m  = &g_msg[(size_t)e * 384];
        const float* vp = &v[(size_t)e * 384];
        float sp0 = m[f], sp1 = m[128 + f], sp2 = m[256 + f];
        float r0 = __ldg(&r[e * 3]), r1 = __ldg(&r[e * 3 + 1]), r2 = __ldg(&r[e * 3 + 2]);
        a0 += sp2 * (r0 * ginv) + sp0 * vp[f];
        a1 += sp2 * (r1 * ginv) + sp0 * vp[128 + f];
        a2 += sp2 * (r2 * ginv) + sp0 * vp[256 + f];
        as += sp1;
    }
    size_t ob = (size_t)n * 384;
    out[ob + f]       = a0;
    out[ob + 128 + f] = a1;
    out[ob + 256 + f] = a2;
    out[OUT_S_OFF + (size_t)n * 128 + f] = as;
}

extern "C" void kernel_launch(void* const* d_in, const int* in_sizes, int n_in,
                              void* d_out, int out_size) {
    const float* s    = (const float*)d_in[0];
    const float* r    = (const float*)d_in[1];
    const float* v    = (const float*)d_in[2];
    const int*   idx  = (const int*)d_in[3];
    const float* Wphi = (const float*)d_in[4];
    const float* bphi = (const float*)d_in[5];
    const float* Ww   = (const float*)d_in[6];
    const float* bw   = (const float*)d_in[7];
    float* out = (float*)d_out;

    cudaFuncSetAttribute(gemm_kernel,
                         cudaFuncAttributeMaxDynamicSharedMemorySize, SMEM_SZ);
    gemm_kernel<<<dim3(148, 3), 512, SMEM_SZ>>>(s, r, Wphi, bphi, Ww, bw);

    reset_kernel<<<64, 256>>>();
    hist_sumsq_kernel<<<256, 256>>>(idx, r);
    scan_kernel<<<1, 1024>>>();
    fill_kernel<<<256, 256>>>(idx);

    gather_kernel<<<N_NODES, 128>>>(r, v, out);
}

// round 6
// speedup vs baseline: 1.0399x; 1.0399x over previous
#include <cuda_runtime.h>
#include <cuda_bf16.h>
#include <cstdint>
#include <cstddef>

#define E_EDGES 320000
#define N_NODES 20000
#define N_RBF   20
#define TILE_E  128
#define NTILES  2500
#define OUT_S_OFF ((size_t)N_NODES * 3 * 128)
#define PF      132     // fp32 pitch for A/B tiles (conflict-free frags)
#define WPITCH  40      // bf16 pitch for rbf & Ww tiles (K padded to 32)

typedef unsigned long long ull;

// ---- device scratch ----
__device__ float  g_msg[(size_t)E_EDGES * 384];
__device__ int    g_hist[N_NODES];
__device__ int    g_cursor[N_NODES];
__device__ int    g_off[N_NODES + 1];
__device__ int    g_elist[E_EDGES];
__device__ double g_sumsq;

// ---- f32x2 helpers ----
__device__ __forceinline__ ull pack2(float lo, float hi) {
    ull r; asm("mov.b64 %0, {%1,%2};" : "=l"(r) : "f"(lo), "f"(hi)); return r;
}
__device__ __forceinline__ ull mul2(ull a, ull b) {
    ull d; asm("mul.rn.f32x2 %0, %1, %2;" : "=l"(d) : "l"(a), "l"(b)); return d;
}
__device__ __forceinline__ ull add2(ull a, ull b) {
    ull d; asm("add.rn.f32x2 %0, %1, %2;" : "=l"(d) : "l"(a), "l"(b)); return d;
}

// ---- tensor-core mma wrappers (baseline PTX) ----
__device__ __forceinline__ void mma_tf32(float* d, uint32_t a0, uint32_t a1,
                                         uint32_t a2, uint32_t a3,
                                         uint32_t b0, uint32_t b1) {
    asm volatile(
        "mma.sync.aligned.m16n8k8.row.col.f32.tf32.tf32.f32 "
        "{%0,%1,%2,%3}, {%4,%5,%6,%7}, {%8,%9}, {%0,%1,%2,%3};"
        : "+f"(d[0]), "+f"(d[1]), "+f"(d[2]), "+f"(d[3])
        : "r"(a0), "r"(a1), "r"(a2), "r"(a3), "r"(b0), "r"(b1));
}
__device__ __forceinline__ void mma_bf16(float* d, uint32_t a0, uint32_t a1,
                                         uint32_t a2, uint32_t a3,
                                         uint32_t b0, uint32_t b1) {
    asm volatile(
        "mma.sync.aligned.m16n8k16.row.col.f32.bf16.bf16.f32 "
        "{%0,%1,%2,%3}, {%4,%5,%6,%7}, {%8,%9}, {%0,%1,%2,%3};"
        : "+f"(d[0]), "+f"(d[1]), "+f"(d[2]), "+f"(d[3])
        : "r"(a0), "r"(a1), "r"(a2), "r"(a3), "r"(b0), "r"(b1));
}
__device__ __forceinline__ uint32_t tf32cvt(float x) {
    uint32_t r; asm("cvt.rna.tf32.f32 %0, %1;" : "=r"(r) : "f"(x)); return r;
}
__device__ __forceinline__ void split1(float x, __nv_bfloat16& h, __nv_bfloat16& l) {
    h = __float2bfloat16(x);
    l = __float2bfloat16(x - __bfloat162float(h));
}

// smem byte offsets
#define OFF_A    0                // 128*132*4 = 67584 (aliased by sp buffer)
#define OFF_B    67584            // 67584
#define OFF_WWH  135168           // 128*40*2 = 10240
#define OFF_WWL  145408
#define OFF_RBFH 155648
#define OFF_RBFL 165888
#define OFF_BPHI 176128           // fp32 128
#define OFF_BW   176640
#define SMEM_SZ  177152

// ---- CSR/misc kernels ----
__global__ void reset_kernel() {
    int i = blockIdx.x * blockDim.x + threadIdx.x;
    if (i == 0) g_sumsq = 0.0;
    int st = gridDim.x * blockDim.x;
    for (int j = i; j < N_NODES; j += st) g_hist[j] = 0;
}
__global__ void hist_sumsq_kernel(const int* __restrict__ idx,
                                  const float* __restrict__ r) {
    int i = blockIdx.x * blockDim.x + threadIdx.x;
    int st = gridDim.x * blockDim.x;
    for (int e = i; e < E_EDGES; e += st) atomicAdd(&g_hist[idx[e]], 1);
    float s = 0.f;
    for (int j = i; j < E_EDGES * 3; j += st) { float x = r[j]; s += x * x; }
    #pragma unroll
    for (int o = 16; o > 0; o >>= 1) s += __shfl_down_sync(0xffffffffu, s, o);
    __shared__ float ws[8];
    if ((threadIdx.x & 31) == 0) ws[threadIdx.x >> 5] = s;
    __syncthreads();
    if (threadIdx.x < 8) {
        float t = ws[threadIdx.x];
        #pragma unroll
        for (int o = 4; o > 0; o >>= 1) t += __shfl_down_sync(0xffu, t, o);
        if (threadIdx.x == 0) atomicAdd(&g_sumsq, (double)t);
    }
}
__global__ void __launch_bounds__(1024) scan_kernel() {
    const int CH = 20;
    __shared__ int wsum[32];
    int t = threadIdx.x, lane = t & 31, w = t >> 5;
    int base = t * CH;
    int h[CH];
    int s = 0;
    #pragma unroll
    for (int i = 0; i < CH; i++) {
        int j = base + i;
        h[i] = (j < N_NODES) ? g_hist[j] : 0;
        s += h[i];
    }
    int ps = s;
    #pragma unroll
    for (int o = 1; o < 32; o <<= 1) {
        int u = __shfl_up_sync(0xffffffffu, ps, o);
        if (lane >= o) ps += u;
    }
    if (lane == 31) wsum[w] = ps;
    __syncthreads();
    if (w == 0) {
        int v = wsum[lane];
        #pragma unroll
        for (int o = 1; o < 32; o <<= 1) {
            int u = __shfl_up_sync(0xffffffffu, v, o);
            if (lane >= o) v += u;
        }
        wsum[lane] = v;
    }
    __syncthreads();
    int run = ps - s + ((w > 0) ? wsum[w - 1] : 0);
    #pragma unroll
    for (int i = 0; i < CH; i++) {
        int j = base + i;
        if (j < N_NODES) { g_off[j] = run; g_cursor[j] = run; run += h[i]; }
    }
    if (t == 1023) g_off[N_NODES] = run;
}
__global__ void fill_kernel(const int* __restrict__ idx) {
    int i = blockIdx.x * blockDim.x + threadIdx.x;
    int st = gridDim.x * blockDim.x;
    for (int e = i; e < E_EDGES; e += st)
        g_elist[atomicAdd(&g_cursor[idx[e]], 1)] = e;
}

// ---- tensor-core GEMM (TF32 phi + bf16 w) -> g_msg. grid (X, 3) ----
__global__ void __launch_bounds__(512, 1)
gemm_kernel(const float* __restrict__ s, const float* __restrict__ r,
            const float* __restrict__ Wphi, const float* __restrict__ bphi,
            const float* __restrict__ Ww, const float* __restrict__ bw)
{
    extern __shared__ char sm[];
    uint32_t* A_s = (uint32_t*)(sm + OFF_A);    // tf32, pitch PF
    uint32_t* B_s = (uint32_t*)(sm + OFF_B);    // tf32, [n][k] pitch PF
    __nv_bfloat16* Wwh = (__nv_bfloat16*)(sm + OFF_WWH);
    __nv_bfloat16* Wwl = (__nv_bfloat16*)(sm + OFF_WWL);
    __nv_bfloat16* Rbh = (__nv_bfloat16*)(sm + OFF_RBFH);
    __nv_bfloat16* Rbl = (__nv_bfloat16*)(sm + OFF_RBFL);
    float* bphi_s = (float*)(sm + OFF_BPHI);
    float* bw_s   = (float*)(sm + OFF_BW);
    float* sp     = (float*)(sm + OFF_A);       // alias, pitch PF

    const int tid  = threadIdx.x;
    const int wid  = tid >> 5;
    const int lane = tid & 31;
    const int g    = lane >> 2;
    const int t4   = lane & 3;
    const int mt   = wid >> 1;
    const int nh   = wid & 1;
    const int group = blockIdx.y;
    const int goff  = group * 128;

    // ---- one-time weights ----
    for (int i = tid; i < 128 * 128; i += 512) {
        int n = i >> 7, k = i & 127;
        B_s[n * PF + k] = tf32cvt(Wphi[k * 384 + goff + n]);
    }
    for (int i = tid; i < 128 * 32; i += 512) {
        int n = i >> 5, k = i & 31;
        float x = (k < N_RBF) ? Ww[k * 384 + goff + n] : 0.f;
        __nv_bfloat16 h, l;
        split1(x, h, l);
        Wwh[n * WPITCH + k] = h;
        Wwl[n * WPITCH + k] = l;
    }
    if (tid < 128) { bphi_s[tid] = bphi[goff + tid]; bw_s[tid] = bw[goff + tid]; }
    __syncthreads();

    const int eL  = tid >> 2;
    const int cbL = (tid & 3) * 32;
    const int e0  = mt * 16 + g;
    const int e1  = e0 + 8;

    for (int tile = blockIdx.x; tile < NTILES; tile += gridDim.x) {
        const int ebase = tile * TILE_E;

        // 1) s-tile loads
        float4 st4[8];
        {
            const float* p = &s[(size_t)(ebase + eL) * 128 + cbL];
            #pragma unroll
            for (int q = 0; q < 8; q++) st4[q] = __ldg((const float4*)p + q);
        }

        // 2) rbf (hi/lo bf16, K padded to 32)
        for (int i = tid; i < TILE_E * 32; i += 512) {
            int el = i >> 5, n = i & 31;
            float x = 0.f;
            if (n < N_RBF) {
                float rx = __ldg(&r[(ebase + el) * 3]);
                float ry = __ldg(&r[(ebase + el) * 3 + 1]);
                float rz = __ldg(&r[(ebase + el) * 3 + 2]);
                float rn = sqrtf(rx * rx + ry * ry + rz * rz);
                float tt = sinf((float)(n + 1) * (3.14159265358979323846f / 5.0f) * rn) / rn;
                x = (tt <= 5.0f)
                    ? 0.5f * (cosf(3.14159265358979323846f * 0.2f * tt) + 1.0f) : 0.0f;
            }
            __nv_bfloat16 h, l;
            split1(x, h, l);
            Rbh[el * WPITCH + n] = h;
            Rbl[el * WPITCH + n] = l;
        }
        __syncthreads();   // rbf ready; prev sp copy-out done (A region free)

        // 3) w-GEMM (bf16 3-term, K=32)
        float acc_w[8][4];
        #pragma unroll
        for (int j = 0; j < 8; j++)
            acc_w[j][0] = acc_w[j][1] = acc_w[j][2] = acc_w[j][3] = 0.f;
        #pragma unroll
        for (int kk = 0; kk < 2; kk++) {
            const int kb = kk * 16 + t4 * 2;
            uint32_t ah0 = *(uint32_t*)&Rbh[e0 * WPITCH + kb];
            uint32_t ah1 = *(uint32_t*)&Rbh[e1 * WPITCH + kb];
            uint32_t ah2 = *(uint32_t*)&Rbh[e0 * WPITCH + kb + 8];
            uint32_t ah3 = *(uint32_t*)&Rbh[e1 * WPITCH + kb + 8];
            uint32_t al0 = *(uint32_t*)&Rbl[e0 * WPITCH + kb];
            uint32_t al1 = *(uint32_t*)&Rbl[e1 * WPITCH + kb];
            uint32_t al2 = *(uint32_t*)&Rbl[e0 * WPITCH + kb + 8];
            uint32_t al3 = *(uint32_t*)&Rbl[e1 * WPITCH + kb + 8];
            #pragma unroll
            for (int j = 0; j < 8; j++) {
                int nrow = (nh * 64 + j * 8 + g) * WPITCH + kb;
                uint32_t bh0 = *(uint32_t*)&Wwh[nrow];
                uint32_t bh1 = *(uint32_t*)&Wwh[nrow + 8];
                uint32_t bl0 = *(uint32_t*)&Wwl[nrow];
                uint32_t bl1 = *(uint32_t*)&Wwl[nrow + 8];
                mma_bf16(acc_w[j], ah0, ah1, ah2, ah3, bh0, bh1);
                mma_bf16(acc_w[j], ah0, ah1, ah2, ah3, bl0, bl1);
                mma_bf16(acc_w[j], al0, al1, al2, al3, bh0, bh1);
            }
        }

        // 4) staged s -> A_s as tf32
        #pragma unroll
        for (int b = 0; b < 8; b++) {
            uint4 t;
            t.x = tf32cvt(st4[b].x); t.y = tf32cvt(st4[b].y);
            t.z = tf32cvt(st4[b].z); t.w = tf32cvt(st4[b].w);
            *(uint4*)&A_s[eL * PF + cbL + b * 4] = t;
        }
        __syncthreads();

        // 5) main MMA: phi via TF32, 16 k-steps x 8 n-tiles
        float acc[8][4];
        #pragma unroll
        for (int j = 0; j < 8; j++)
            acc[j][0] = acc[j][1] = acc[j][2] = acc[j][3] = 0.f;
        #pragma unroll 1
        for (int kk = 0; kk < 16; kk++) {
            const int kb = kk * 8 + t4;
            uint32_t a0 = A_s[e0 * PF + kb];
            uint32_t a1 = A_s[e1 * PF + kb];
            uint32_t a2 = A_s[e0 * PF + kb + 4];
            uint32_t a3 = A_s[e1 * PF + kb + 4];
            #pragma unroll
            for (int j = 0; j < 8; j++) {
                int nrow = (nh * 64 + j * 8 + g) * PF + kb;
                uint32_t b0 = B_s[nrow];
                uint32_t b1 = B_s[nrow + 4];
                mma_tf32(acc[j], a0, a1, a2, a3, b0, b1);
            }
        }
        __syncthreads();   // A reads done before sp overwrite

        // 6) sp = (acc_w + bw) * (acc + bphi) -> smem transpose (pitch PF)
        #pragma unroll
        for (int j = 0; j < 8; j++) {
            int cj = nh * 64 + j * 8 + t4 * 2;
            ull bp  = *(ull*)&bphi_s[cj];
            ull bwj = *(ull*)&bw_s[cj];
            ull w0 = add2(pack2(acc_w[j][0], acc_w[j][1]), bwj);
            ull w1 = add2(pack2(acc_w[j][2], acc_w[j][3]), bwj);
            ull p0 = mul2(w0, add2(pack2(acc[j][0], acc[j][1]), bp));
            ull p1 = mul2(w1, add2(pack2(acc[j][2], acc[j][3]), bp));
            *(ull*)&sp[e0 * PF + cj] = p0;
            *(ull*)&sp[e1 * PF + cj] = p1;
        }
        __syncthreads();

        // 7) coalesced copy-out
        #pragma unroll
        for (int kk = 0; kk < 8; kk++) {
            int i = kk * 512 + tid;
            int edge = i >> 5, ch = i & 31;
            float4 val = *(float4*)&sp[edge * PF + ch * 4];
            *(float4*)&g_msg[(size_t)(ebase + edge) * 384 + goff + ch * 4] = val;
        }
    }
}

// ---- per-node gather ----
__global__ void __launch_bounds__(128)
gather_kernel(const float* __restrict__ r, const float* __restrict__ v,
              float* __restrict__ out)
{
    const int n = blockIdx.x;
    const int f = threadIdx.x;
    const float ginv = (float)(1.0 / sqrt(g_sumsq));
    const int beg = g_off[n], end = g_off[n + 1];

    float a0 = 0.f, a1 = 0.f, a2 = 0.f, as = 0.f;
    int p = beg;
    #pragma unroll 1
    for (; p + 2 <= end; p += 2) {
        const int ea = g_elist[p], eb = g_elist[p + 1];
        const float* ma = &g_msg[(size_t)ea * 384];
        const float* mb = &g_msg[(size_t)eb * 384];
        const float* va = &v[(size_t)ea * 384];
        const float* vb = &v[(size_t)eb * 384];
        float s0a = ma[f], s1a = ma[128 + f], s2a = ma[256 + f];
        float s0b = mb[f], s1b = mb[128 + f], s2b = mb[256 + f];
        float va0 = va[f], va1 = va[128 + f], va2 = va[256 + f];
        float vb0 = vb[f], vb1 = vb[128 + f], vb2 = vb[256 + f];
        float ra0 = __ldg(&r[ea * 3]), ra1 = __ldg(&r[ea * 3 + 1]), ra2 = __ldg(&r[ea * 3 + 2]);
        float rb0 = __ldg(&r[eb * 3]), rb1 = __ldg(&r[eb * 3 + 1]), rb2 = __ldg(&r[eb * 3 + 2]);
        a0 += s2a * (ra0 * ginv) + s0a * va0 + s2b * (rb0 * ginv) + s0b * vb0;
        a1 += s2a * (ra1 * ginv) + s0a * va1 + s2b * (rb1 * ginv) + s0b * vb1;
        a2 += s2a * (ra2 * ginv) + s0a * va2 + s2b * (rb2 * ginv) + s0b * vb2;
        as += s1a + s1b;
    }
    if (p < end) {
        const int e = g_elist[p];
        const float* m  = &g_msg[(size_t)e * 384];
        const float* vp = &v[(size_t)e * 384];
        float sp0 = m[f], sp1 = m[128 + f], sp2 = m[256 + f];
        float r0 = __ldg(&r[e * 3]), r1 = __ldg(&r[e * 3 + 1]), r2 = __ldg(&r[e * 3 + 2]);
        a0 += sp2 * (r0 * ginv) + sp0 * vp[f];
        a1 += sp2 * (r1 * ginv) + sp0 * vp[128 + f];
        a2 += sp2 * (r2 * ginv) + sp0 * vp[256 + f];
        as += sp1;
    }
    size_t ob = (size_t)n * 384;
    out[ob + f]       = a0;
    out[ob + 128 + f] = a1;
    out[ob + 256 + f] = a2;
    out[OUT_S_OFF + (size_t)n * 128 + f] = as;
}

extern "C" void kernel_launch(void* const* d_in, const int* in_sizes, int n_in,
                              void* d_out, int out_size) {
    const float* s    = (const float*)d_in[0];
    const float* r    = (const float*)d_in[1];
    const float* v    = (const float*)d_in[2];
    const int*   idx  = (const int*)d_in[3];
    const float* Wphi = (const float*)d_in[4];
    const float* bphi = (const float*)d_in[5];
    const float* Ww   = (const float*)d_in[6];
    const float* bw   = (const float*)d_in[7];
    float* out = (float*)d_out;

    // host-side resources, created once (no device memory involved)
    static cudaStream_t s2 = nullptr;
    static cudaEvent_t evFork = nullptr, evJoin = nullptr;
    if (s2 == nullptr) {
        cudaStreamCreateWithFlags(&s2, cudaStreamNonBlocking);
        cudaEventCreateWithFlags(&evFork, cudaEventDisableTiming);
        cudaEventCreateWithFlags(&evJoin, cudaEventDisableTiming);
    }

    // fork: CSR chain on s2, GEMM on main stream (independent work)
    cudaEventRecord(evFork, 0);
    cudaStreamWaitEvent(s2, evFork, 0);

    reset_kernel<<<64, 256, 0, s2>>>();
    hist_sumsq_kernel<<<256, 256, 0, s2>>>(idx, r);
    scan_kernel<<<1, 1024, 0, s2>>>();
    fill_kernel<<<256, 256, 0, s2>>>(idx);
    cudaEventRecord(evJoin, s2);

    cudaFuncSetAttribute(gemm_kernel,
                         cudaFuncAttributeMaxDynamicSharedMemorySize, SMEM_SZ);
    gemm_kernel<<<dim3(148, 3), 512, SMEM_SZ>>>(s, r, Wphi, bphi, Ww, bw);

    // join: gather needs both g_msg (main) and CSR/g_sumsq (s2)
    cudaStreamWaitEvent(0, evJoin, 0);
    gather_kernel<<<N_NODES, 128>>>(r, v, out);
}

// round 7
// speedup vs baseline: 1.2769x; 1.2279x over previous
#include <cuda_runtime.h>
#include <cuda_bf16.h>
#include <cstdint>
#include <cstddef>

#define E_EDGES 320000
#define N_NODES 20000
#define N_RBF   20
#define TILE_E  128
#define NTILES  2500
#define OUT_S_OFF ((size_t)N_NODES * 3 * 128)
#define PITCH   136     // bf16/row, A & B tiles
#define WPITCH  40      // bf16/row, rbf & Ww tiles (K padded to 32)
#define PF      132     // fp32 pitch for sp transpose buffer

typedef unsigned long long ull;

// ---- device scratch ----
__device__ float          g_msg[(size_t)E_EDGES * 384];
__device__ __nv_bfloat16  g_rbfh[(size_t)E_EDGES * 32];
__device__ __nv_bfloat16  g_rbfl[(size_t)E_EDGES * 32];
__device__ int    g_hist[N_NODES];
__device__ int    g_cursor[N_NODES];
__device__ int    g_off[N_NODES + 1];
__device__ int    g_elist[E_EDGES];
__device__ double g_sumsq;

// ---- f32x2 helpers ----
__device__ __forceinline__ ull pack2(float lo, float hi) {
    ull r; asm("mov.b64 %0, {%1,%2};" : "=l"(r) : "f"(lo), "f"(hi)); return r;
}
__device__ __forceinline__ ull mul2(ull a, ull b) {
    ull d; asm("mul.rn.f32x2 %0, %1, %2;" : "=l"(d) : "l"(a), "l"(b)); return d;
}
__device__ __forceinline__ ull add2(ull a, ull b) {
    ull d; asm("add.rn.f32x2 %0, %1, %2;" : "=l"(d) : "l"(a), "l"(b)); return d;
}

// ---- tensor-core primitives (baseline PTX) ----
__device__ __forceinline__ void mma_bf16(float* d, uint32_t a0, uint32_t a1,
                                         uint32_t a2, uint32_t a3,
                                         uint32_t b0, uint32_t b1) {
    asm volatile(
        "mma.sync.aligned.m16n8k16.row.col.f32.bf16.bf16.f32 "
        "{%0,%1,%2,%3}, {%4,%5,%6,%7}, {%8,%9}, {%0,%1,%2,%3};"
        : "+f"(d[0]), "+f"(d[1]), "+f"(d[2]), "+f"(d[3])
        : "r"(a0), "r"(a1), "r"(a2), "r"(a3), "r"(b0), "r"(b1));
}
__device__ __forceinline__ void ldsm4(uint32_t& r0, uint32_t& r1,
                                      uint32_t& r2, uint32_t& r3, uint32_t a) {
    asm volatile("ldmatrix.sync.aligned.m8n8.x4.shared.b16 {%0,%1,%2,%3}, [%4];"
                 : "=r"(r0), "=r"(r1), "=r"(r2), "=r"(r3) : "r"(a));
}
__device__ __forceinline__ uint32_t smem_u32(const void* p) {
    uint32_t a;
    asm("{ .reg .u64 t; cvta.to.shared.u64 t, %1; cvt.u32.u64 %0, t; }"
        : "=r"(a) : "l"(p));
    return a;
}
__device__ __forceinline__ void split1(float x, __nv_bfloat16& h, __nv_bfloat16& l) {
    h = __float2bfloat16(x);
    l = __float2bfloat16(x - __bfloat162float(h));
}
__device__ __forceinline__ void split2(float x0, float x1, uint32_t& hi, uint32_t& lo) {
    __nv_bfloat162 h = __floats2bfloat162_rn(x0, x1);
    float h0 = __low2float(h), h1 = __high2float(h);
    __nv_bfloat162 l = __floats2bfloat162_rn(x0 - h0, x1 - h1);
    hi = *reinterpret_cast<uint32_t*>(&h);
    lo = *reinterpret_cast<uint32_t*>(&l);
}

// smem byte offsets
#define OFF_AHI  0                // 128*136*2 = 34816
#define OFF_ALO  34816
#define OFF_BHI  69632
#define OFF_BLO  104448
#define OFF_WWH  139264           // 128*40*2 = 10240
#define OFF_WWL  149504
#define OFF_RBH  159744
#define OFF_RBL  169984
#define OFF_BPHI 180224
#define OFF_BW   180736
#define SMEM_SZ  181248
// sp transpose buffer aliases A region: 128*132*4 = 67584 <= 69632

// ---- rbf precompute ----
__global__ void rbf_kernel(const float* __restrict__ r) {
    int i = blockIdx.x * blockDim.x + threadIdx.x;
    int st = gridDim.x * blockDim.x;
    for (; i < E_EDGES * 32; i += st) {
        int e = i >> 5, n = i & 31;
        float x = 0.f;
        if (n < N_RBF) {
            float rx = __ldg(&r[e * 3]);
            float ry = __ldg(&r[e * 3 + 1]);
            float rz = __ldg(&r[e * 3 + 2]);
            float rn = sqrtf(rx * rx + ry * ry + rz * rz);
            float tt = sinf((float)(n + 1) * (3.14159265358979323846f / 5.0f) * rn) / rn;
            x = (tt <= 5.0f)
                ? 0.5f * (cosf(3.14159265358979323846f * 0.2f * tt) + 1.0f) : 0.0f;
        }
        __nv_bfloat16 h, l;
        split1(x, h, l);
        g_rbfh[i] = h;
        g_rbfl[i] = l;
    }
}

// ---- CSR/misc kernels ----
__global__ void reset_kernel() {
    int i = blockIdx.x * blockDim.x + threadIdx.x;
    if (i == 0) g_sumsq = 0.0;
    int st = gridDim.x * blockDim.x;
    for (int j = i; j < N_NODES; j += st) g_hist[j] = 0;
}
__global__ void hist_sumsq_kernel(const int* __restrict__ idx,
                                  const float* __restrict__ r) {
    int i = blockIdx.x * blockDim.x + threadIdx.x;
    int st = gridDim.x * blockDim.x;
    for (int e = i; e < E_EDGES; e += st) atomicAdd(&g_hist[idx[e]], 1);
    float s = 0.f;
    for (int j = i; j < E_EDGES * 3; j += st) { float x = r[j]; s += x * x; }
    #pragma unroll
    for (int o = 16; o > 0; o >>= 1) s += __shfl_down_sync(0xffffffffu, s, o);
    __shared__ float ws[8];
    if ((threadIdx.x & 31) == 0) ws[threadIdx.x >> 5] = s;
    __syncthreads();
    if (threadIdx.x < 8) {
        float t = ws[threadIdx.x];
        #pragma unroll
        for (int o = 4; o > 0; o >>= 1) t += __shfl_down_sync(0xffu, t, o);
        if (threadIdx.x == 0) atomicAdd(&g_sumsq, (double)t);
    }
}
__global__ void __launch_bounds__(1024) scan_kernel() {
    const int CH = 20;
    __shared__ int wsum[32];
    int t = threadIdx.x, lane = t & 31, w = t >> 5;
    int base = t * CH;
    int h[CH];
    int s = 0;
    #pragma unroll
    for (int i = 0; i < CH; i++) {
        int j = base + i;
        h[i] = (j < N_NODES) ? g_hist[j] : 0;
        s += h[i];
    }
    int ps = s;
    #pragma unroll
    for (int o = 1; o < 32; o <<= 1) {
        int u = __shfl_up_sync(0xffffffffu, ps, o);
        if (lane >= o) ps += u;
    }
    if (lane == 31) wsum[w] = ps;
    __syncthreads();
    if (w == 0) {
        int v = wsum[lane];
        #pragma unroll
        for (int o = 1; o < 32; o <<= 1) {
            int u = __shfl_up_sync(0xffffffffu, v, o);
            if (lane >= o) v += u;
        }
        wsum[lane] = v;
    }
    __syncthreads();
    int run = ps - s + ((w > 0) ? wsum[w - 1] : 0);
    #pragma unroll
    for (int i = 0; i < CH; i++) {
        int j = base + i;
        if (j < N_NODES) { g_off[j] = run; g_cursor[j] = run; run += h[i]; }
    }
    if (t == 1023) g_off[N_NODES] = run;
}
__global__ void fill_kernel(const int* __restrict__ idx) {
    int i = blockIdx.x * blockDim.x + threadIdx.x;
    int st = gridDim.x * blockDim.x;
    for (int e = i; e < E_EDGES; e += st)
        g_elist[atomicAdd(&g_cursor[idx[e]], 1)] = e;
}

// ---- tensor-core GEMM (bf16 3-term, ldmatrix-fed) -> g_msg. grid (X, 3) ----
__global__ void __launch_bounds__(512, 1)
gemm_kernel(const float* __restrict__ s,
            const float* __restrict__ Wphi, const float* __restrict__ bphi,
            const float* __restrict__ Ww, const float* __restrict__ bw)
{
    extern __shared__ char sm[];
    float* bphi_s = (float*)(sm + OFF_BPHI);
    float* bw_s   = (float*)(sm + OFF_BW);
    float* sp     = (float*)(sm + OFF_AHI);     // alias, pitch PF

    const int tid  = threadIdx.x;
    const int wid  = tid >> 5;
    const int lane = tid & 31;
    const int mt   = wid >> 1;       // m-tile 0..7 (rows mt*16..+15)
    const int nh   = wid & 1;        // n-half (cols nh*64..+63)
    const int group = blockIdx.y;
    const int goff  = group * 128;
    const uint32_t smb = smem_u32(sm);

    // ---- one-time weights into smem ----
    {
        __nv_bfloat16* B_hi = (__nv_bfloat16*)(sm + OFF_BHI);
        __nv_bfloat16* B_lo = (__nv_bfloat16*)(sm + OFF_BLO);
        __nv_bfloat16* Wwh  = (__nv_bfloat16*)(sm + OFF_WWH);
        __nv_bfloat16* Wwl  = (__nv_bfloat16*)(sm + OFF_WWL);
        for (int i = tid; i < 128 * 128; i += 512) {
            int n = i >> 7, k = i & 127;
            __nv_bfloat16 h, l;
            split1(Wphi[k * 384 + goff + n], h, l);
            B_hi[n * PITCH + k] = h;
            B_lo[n * PITCH + k] = l;
        }
        for (int i = tid; i < 128 * 32; i += 512) {
            int n = i >> 5, k = i & 31;
            float x = (k < N_RBF) ? Ww[k * 384 + goff + n] : 0.f;
            __nv_bfloat16 h, l;
            split1(x, h, l);
            Wwh[n * WPITCH + k] = h;
            Wwl[n * WPITCH + k] = l;
        }
        if (tid < 128) { bphi_s[tid] = bphi[goff + tid]; bw_s[tid] = bw[goff + tid]; }
    }
    __syncthreads();

    // per-thread ldmatrix address components
    const int arow = mt * 16 + (lane & 15);        // A-frag row
    const int acol = (lane >> 4) << 3;             // A-frag k-half (0/8)
    const int brl  = ((lane >> 4) << 3) + (lane & 7);  // B-frag local row in 16-block
    const int bk   = ((lane >> 3) & 1) << 3;       // B-frag k-half (0/8)

    const uint32_t aH = smb + OFF_AHI + (uint32_t)(arow * PITCH + acol) * 2;
    const uint32_t aL = smb + OFF_ALO + (uint32_t)(arow * PITCH + acol) * 2;
    const uint32_t bH = smb + OFF_BHI + (uint32_t)((nh * 64 + brl) * PITCH + bk) * 2;
    const uint32_t bL = smb + OFF_BLO + (uint32_t)((nh * 64 + brl) * PITCH + bk) * 2;
    const uint32_t rH = smb + OFF_RBH + (uint32_t)(arow * WPITCH + acol) * 2;
    const uint32_t rL = smb + OFF_RBL + (uint32_t)(arow * WPITCH + acol) * 2;
    const uint32_t wH = smb + OFF_WWH + (uint32_t)((nh * 64 + brl) * WPITCH + bk) * 2;
    const uint32_t wL = smb + OFF_WWL + (uint32_t)((nh * 64 + brl) * WPITCH + bk) * 2;

    const int eL  = tid >> 2;           // staging: edge row
    const int cbL = (tid & 3) * 32;     // staging: col base
    const int ep0 = mt * 16 + (lane >> 2);   // epilogue rows
    const int ep1 = ep0 + 8;
    const int t4  = lane & 3;

    for (int tile = blockIdx.x; tile < NTILES; tile += gridDim.x) {
        const int ebase = tile * TILE_E;

        // ---- stage A (s-tile, hi/lo split) + rbf tiles ----
        {
            __nv_bfloat16* A_hi = (__nv_bfloat16*)(sm + OFF_AHI);
            __nv_bfloat16* A_lo = (__nv_bfloat16*)(sm + OFF_ALO);
            const float* p = &s[(size_t)(ebase + eL) * 128 + cbL];
            #pragma unroll
            for (int b = 0; b < 8; b++) {
                float4 x = __ldg((const float4*)p + b);
                uint2 hi, lo;
                split2(x.x, x.y, hi.x, lo.x);
                split2(x.z, x.w, hi.y, lo.y);
                int o = eL * PITCH + cbL + b * 4;
                *(uint2*)&A_hi[o] = hi;
                *(uint2*)&A_lo[o] = lo;
            }
            // rbf: 128 rows x 32 bf16 (64B) per buffer; 512 threads = 4 x 16B per row
            int row = tid >> 2, seg = tid & 3;
            const uint4* ph = (const uint4*)&g_rbfh[(size_t)(ebase + row) * 32];
            const uint4* pl = (const uint4*)&g_rbfl[(size_t)(ebase + row) * 32];
            __nv_bfloat16* Rbh = (__nv_bfloat16*)(sm + OFF_RBH);
            __nv_bfloat16* Rbl = (__nv_bfloat16*)(sm + OFF_RBL);
            *(uint4*)&Rbh[row * WPITCH + seg * 8] = __ldg(ph + seg);
            *(uint4*)&Rbl[row * WPITCH + seg * 8] = __ldg(pl + seg);
        }
        __syncthreads();

        // ---- w-GEMM: acc_w = rbf @ Ww (3-term, K=32, ldmatrix) ----
        float acc_w[8][4];
        #pragma unroll
        for (int j = 0; j < 8; j++)
            acc_w[j][0] = acc_w[j][1] = acc_w[j][2] = acc_w[j][3] = 0.f;
        #pragma unroll
        for (int kk = 0; kk < 2; kk++) {
            const uint32_t ko = kk * 32;   // 16 elems * 2B
            uint32_t ah0, ah1, ah2, ah3, al0, al1, al2, al3;
            ldsm4(ah0, ah1, ah2, ah3, rH + ko);
            ldsm4(al0, al1, al2, al3, rL + ko);
            #pragma unroll
            for (int jj = 0; jj < 4; jj++) {
                const uint32_t bo = (uint32_t)(jj * 16 * WPITCH) * 2 + ko;
                uint32_t bh0, bh1, bh2, bh3, bl0, bl1, bl2, bl3;
                ldsm4(bh0, bh1, bh2, bh3, wH + bo);
                ldsm4(bl0, bl1, bl2, bl3, wL + bo);
                mma_bf16(acc_w[2*jj],   ah0, ah1, ah2, ah3, bh0, bh1);
                mma_bf16(acc_w[2*jj],   ah0, ah1, ah2, ah3, bl0, bl1);
                mma_bf16(acc_w[2*jj],   al0, al1, al2, al3, bh0, bh1);
                mma_bf16(acc_w[2*jj+1], ah0, ah1, ah2, ah3, bh2, bh3);
                mma_bf16(acc_w[2*jj+1], ah0, ah1, ah2, ah3, bl2, bl3);
                mma_bf16(acc_w[2*jj+1], al0, al1, al2, al3, bh2, bh3);
            }
        }

        // ---- main GEMM: acc = s @ Wphi (3-term, K=128, ldmatrix) ----
        float acc[8][4];
        #pragma unroll
        for (int j = 0; j < 8; j++)
            acc[j][0] = acc[j][1] = acc[j][2] = acc[j][3] = 0.f;
        #pragma unroll 1
        for (int kk = 0; kk < 8; kk++) {
            const uint32_t ko = kk * 32;   // 16 elems * 2B
            uint32_t ah0, ah1, ah2, ah3, al0, al1, al2, al3;
            ldsm4(ah0, ah1, ah2, ah3, aH + ko);
            ldsm4(al0, al1, al2, al3, aL + ko);
            #pragma unroll
            for (int jj = 0; jj < 4; jj++) {
                const uint32_t bo = (uint32_t)(jj * 16 * PITCH) * 2 + ko;
                uint32_t bh0, bh1, bh2, bh3, bl0, bl1, bl2, bl3;
                ldsm4(bh0, bh1, bh2, bh3, bH + bo);
                ldsm4(bl0, bl1, bl2, bl3, bL + bo);
                mma_bf16(acc[2*jj],   ah0, ah1, ah2, ah3, bh0, bh1);
                mma_bf16(acc[2*jj],   ah0, ah1, ah2, ah3, bl0, bl1);
                mma_bf16(acc[2*jj],   al0, al1, al2, al3, bh0, bh1);
                mma_bf16(acc[2*jj+1], ah0, ah1, ah2, ah3, bh2, bh3);
                mma_bf16(acc[2*jj+1], ah0, ah1, ah2, ah3, bl2, bl3);
                mma_bf16(acc[2*jj+1], al0, al1, al2, al3, bh2, bh3);
            }
        }
        __syncthreads();   // A/rbf reads done before sp overwrite

        // ---- sp = (acc_w + bw) * (acc + bphi) -> smem transpose ----
        #pragma unroll
        for (int j = 0; j < 8; j++) {
            int cj = nh * 64 + j * 8 + t4 * 2;
            ull bp  = *(ull*)&bphi_s[cj];
            ull bwj = *(ull*)&bw_s[cj];
            ull w0 = add2(pack2(acc_w[j][0], acc_w[j][1]), bwj);
            ull w1 = add2(pack2(acc_w[j][2], acc_w[j][3]), bwj);
            ull p0 = mul2(w0, add2(pack2(acc[j][0], acc[j][1]), bp));
            ull p1 = mul2(w1, add2(pack2(acc[j][2], acc[j][3]), bp));
            *(ull*)&sp[ep0 * PF + cj] = p0;
            *(ull*)&sp[ep1 * PF + cj] = p1;
        }
        __syncthreads();

        // ---- coalesced copy-out ----
        #pragma unroll
        for (int kk = 0; kk < 8; kk++) {
            int i = kk * 512 + tid;
            int edge = i >> 5, ch = i & 31;
            float4 val = *(float4*)&sp[edge * PF + ch * 4];
            *(float4*)&g_msg[(size_t)(ebase + edge) * 384 + goff + ch * 4] = val;
        }
        __syncthreads();   // sp region reused as A next iter
    }
}

// ---- per-node gather ----
__global__ void __launch_bounds__(128)
gather_kernel(const float* __restrict__ r, const float* __restrict__ v,
              float* __restrict__ out)
{
    const int n = blockIdx.x;
    const int f = threadIdx.x;
    const float ginv = (float)(1.0 / sqrt(g_sumsq));
    const int beg = g_off[n], end = g_off[n + 1];

    float a0 = 0.f, a1 = 0.f, a2 = 0.f, as = 0.f;
    int p = beg;
    #pragma unroll 1
    for (; p + 2 <= end; p += 2) {
        const int ea = g_elist[p], eb = g_elist[p + 1];
        const float* ma = &g_msg[(size_t)ea * 384];
        const float* mb = &g_msg[(size_t)eb * 384];
        const float* va = &v[(size_t)ea * 384];
        const float* vb = &v[(size_t)eb * 384];
        float s0a = ma[f], s1a = ma[128 + f], s2a = ma[256 + f];
        float s0b = mb[f], s1b = mb[128 + f], s2b = mb[256 + f];
        float va0 = va[f], va1 = va[128 + f], va2 = va[256 + f];
        float vb0 = vb[f], vb1 = vb[128 + f], vb2 = vb[256 + f];
        float ra0 = __ldg(&r[ea * 3]), ra1 = __ldg(&r[ea * 3 + 1]), ra2 = __ldg(&r[ea * 3 + 2]);
        float rb0 = __ldg(&r[eb * 3]), rb1 = __ldg(&r[eb * 3 + 1]), rb2 = __ldg(&r[eb * 3 + 2]);
        a0 += s2a * (ra0 * ginv) + s0a * va0 + s2b * (rb0 * ginv) + s0b * vb0;
        a1 += s2a * (ra1 * ginv) + s0a * va1 + s2b * (rb1 * ginv) + s0b * vb1;
        a2 += s2a * (ra2 * ginv) + s0a * va2 + s2b * (rb2 * ginv) + s0b * vb2;
        as += s1a + s1b;
    }
    if (p < end) {
        const int e = g_elist[p];
        const float* m  = &g_msg[(size_t)e * 384];
        const float* vp = &v[(size_t)e * 384];
        float sp0 = m[f], sp1 = m[128 + f], sp2 = m[256 + f];
        float r0 = __ldg(&r[e * 3]), r1 = __ldg(&r[e * 3 + 1]), r2 = __ldg(&r[e * 3 + 2]);
        a0 += sp2 * (r0 * ginv) + sp0 * vp[f];
        a1 += sp2 * (r1 * ginv) + sp0 * vp[128 + f];
        a2 += sp2 * (r2 * ginv) + sp0 * vp[256 + f];
        as += sp1;
    }
    size_t ob = (size_t)n * 384;
    out[ob + f]       = a0;
    out[ob + 128 + f] = a1;
    out[ob + 256 + f] = a2;
    out[OUT_S_OFF + (size_t)n * 128 + f] = as;
}

extern "C" void kernel_launch(void* const* d_in, const int* in_sizes, int n_in,
                              void* d_out, int out_size) {
    const float* s    = (const float*)d_in[0];
    const float* r    = (const float*)d_in[1];
    const float* v    = (const float*)d_in[2];
    const int*   idx  = (const int*)d_in[3];
    const float* Wphi = (const float*)d_in[4];
    const float* bphi = (const float*)d_in[5];
    const float* Ww   = (const float*)d_in[6];
    const float* bw   = (const float*)d_in[7];
    float* out = (float*)d_out;

    static cudaStream_t s2 = nullptr;
    static cudaEvent_t evFork = nullptr, evJoin = nullptr;
    if (s2 == nullptr) {
        cudaStreamCreateWithFlags(&s2, cudaStreamNonBlocking);
        cudaEventCreateWithFlags(&evFork, cudaEventDisableTiming);
        cudaEventCreateWithFlags(&evJoin, cudaEventDisableTiming);
    }

    // fork: CSR chain on s2; rbf+GEMM on main stream
    cudaEventRecord(evFork, 0);
    cudaStreamWaitEvent(s2, evFork, 0);

    reset_kernel<<<64, 256, 0, s2>>>();
    hist_sumsq_kernel<<<256, 256, 0, s2>>>(idx, r);
    scan_kernel<<<1, 1024, 0, s2>>>();
    fill_kernel<<<256, 256, 0, s2>>>(idx);
    cudaEventRecord(evJoin, s2);

    rbf_kernel<<<2048, 256>>>(r);

    cudaFuncSetAttribute(gemm_kernel,
                         cudaFuncAttributeMaxDynamicSharedMemorySize, SMEM_SZ);
    gemm_kernel<<<dim3(148, 3), 512, SMEM_SZ>>>(s, Wphi, bphi, Ww, bw);

    cudaStreamWaitEvent(0, evJoin, 0);
    gather_kernel<<<N_NODES, 128>>>(r, v, out);
}

// round 8
// speedup vs baseline: 1.2970x; 1.0157x over previous
#include <cuda_runtime.h>
#include <cuda_bf16.h>
#include <cstdint>
#include <cstddef>

#define E_EDGES 320000
#define N_NODES 20000
#define N_RBF   20
#define TILE_E  128
#define NTILES  2500
#define OUT_S_OFF ((size_t)N_NODES * 3 * 128)
#define PITCH   136     // bf16/row, A & B tiles
#define WPITCH  40      // bf16/row, rbf & Ww tiles (K padded to 32)

typedef unsigned long long ull;

// ---- device scratch ----
__device__ float          g_msg[(size_t)E_EDGES * 384];
__device__ __nv_bfloat16  g_rbfh[(size_t)E_EDGES * 32];
__device__ __nv_bfloat16  g_rbfl[(size_t)E_EDGES * 32];
__device__ int    g_hist[N_NODES];
__device__ int    g_cursor[N_NODES];
__device__ int    g_off[N_NODES + 1];
__device__ int    g_elist[E_EDGES];
__device__ double g_sumsq;

// ---- f32x2 helpers ----
__device__ __forceinline__ ull pack2(float lo, float hi) {
    ull r; asm("mov.b64 %0, {%1,%2};" : "=l"(r) : "f"(lo), "f"(hi)); return r;
}
__device__ __forceinline__ ull mul2(ull a, ull b) {
    ull d; asm("mul.rn.f32x2 %0, %1, %2;" : "=l"(d) : "l"(a), "l"(b)); return d;
}
__device__ __forceinline__ ull add2(ull a, ull b) {
    ull d; asm("add.rn.f32x2 %0, %1, %2;" : "=l"(d) : "l"(a), "l"(b)); return d;
}

// ---- tensor-core primitives (baseline PTX) ----
__device__ __forceinline__ void mma_bf16(float* d, uint32_t a0, uint32_t a1,
                                         uint32_t a2, uint32_t a3,
                                         uint32_t b0, uint32_t b1) {
    asm volatile(
        "mma.sync.aligned.m16n8k16.row.col.f32.bf16.bf16.f32 "
        "{%0,%1,%2,%3}, {%4,%5,%6,%7}, {%8,%9}, {%0,%1,%2,%3};"
        : "+f"(d[0]), "+f"(d[1]), "+f"(d[2]), "+f"(d[3])
        : "r"(a0), "r"(a1), "r"(a2), "r"(a3), "r"(b0), "r"(b1));
}
__device__ __forceinline__ void ldsm4(uint32_t& r0, uint32_t& r1,
                                      uint32_t& r2, uint32_t& r3, uint32_t a) {
    asm volatile("ldmatrix.sync.aligned.m8n8.x4.shared.b16 {%0,%1,%2,%3}, [%4];"
                 : "=r"(r0), "=r"(r1), "=r"(r2), "=r"(r3) : "r"(a));
}
__device__ __forceinline__ uint32_t smem_u32(const void* p) {
    uint32_t a;
    asm("{ .reg .u64 t; cvta.to.shared.u64 t, %1; cvt.u32.u64 %0, t; }"
        : "=r"(a) : "l"(p));
    return a;
}
__device__ __forceinline__ void split1(float x, __nv_bfloat16& h, __nv_bfloat16& l) {
    h = __float2bfloat16(x);
    l = __float2bfloat16(x - __bfloat162float(h));
}
__device__ __forceinline__ void split2(float x0, float x1, uint32_t& hi, uint32_t& lo) {
    __nv_bfloat162 h = __floats2bfloat162_rn(x0, x1);
    float h0 = __low2float(h), h1 = __high2float(h);
    __nv_bfloat162 l = __floats2bfloat162_rn(x0 - h0, x1 - h1);
    hi = *reinterpret_cast<uint32_t*>(&h);
    lo = *reinterpret_cast<uint32_t*>(&l);
}

// smem byte offsets
#define OFF_AHI  0                // 128*136*2 = 34816
#define OFF_ALO  34816
#define OFF_BHI  69632
#define OFF_BLO  104448
#define OFF_WWH  139264           // 128*40*2 = 10240
#define OFF_WWL  149504
#define OFF_RBH  159744
#define OFF_RBL  169984
#define OFF_BPHI 180224
#define OFF_BW   180736
#define SMEM_SZ  181248

// ---- rbf precompute ----
__global__ void rbf_kernel(const float* __restrict__ r) {
    int i = blockIdx.x * blockDim.x + threadIdx.x;
    int st = gridDim.x * blockDim.x;
    for (; i < E_EDGES * 32; i += st) {
        int e = i >> 5, n = i & 31;
        float x = 0.f;
        if (n < N_RBF) {
            float rx = __ldg(&r[e * 3]);
            float ry = __ldg(&r[e * 3 + 1]);
            float rz = __ldg(&r[e * 3 + 2]);
            float rn = sqrtf(rx * rx + ry * ry + rz * rz);
            float tt = sinf((float)(n + 1) * (3.14159265358979323846f / 5.0f) * rn) / rn;
            x = (tt <= 5.0f)
                ? 0.5f * (cosf(3.14159265358979323846f * 0.2f * tt) + 1.0f) : 0.0f;
        }
        __nv_bfloat16 h, l;
        split1(x, h, l);
        g_rbfh[i] = h;
        g_rbfl[i] = l;
    }
}

// ---- CSR/misc kernels ----
__global__ void reset_kernel() {
    int i = blockIdx.x * blockDim.x + threadIdx.x;
    if (i == 0) g_sumsq = 0.0;
    int st = gridDim.x * blockDim.x;
    for (int j = i; j < N_NODES; j += st) g_hist[j] = 0;
}
__global__ void hist_sumsq_kernel(const int* __restrict__ idx,
                                  const float* __restrict__ r) {
    int i = blockIdx.x * blockDim.x + threadIdx.x;
    int st = gridDim.x * blockDim.x;
    for (int e = i; e < E_EDGES; e += st) atomicAdd(&g_hist[idx[e]], 1);
    float s = 0.f;
    for (int j = i; j < E_EDGES * 3; j += st) { float x = r[j]; s += x * x; }
    #pragma unroll
    for (int o = 16; o > 0; o >>= 1) s += __shfl_down_sync(0xffffffffu, s, o);
    __shared__ float ws[8];
    if ((threadIdx.x & 31) == 0) ws[threadIdx.x >> 5] = s;
    __syncthreads();
    if (threadIdx.x < 8) {
        float t = ws[threadIdx.x];
        #pragma unroll
        for (int o = 4; o > 0; o >>= 1) t += __shfl_down_sync(0xffu, t, o);
        if (threadIdx.x == 0) atomicAdd(&g_sumsq, (double)t);
    }
}
__global__ void __launch_bounds__(1024) scan_kernel() {
    const int CH = 20;
    __shared__ int wsum[32];
    int t = threadIdx.x, lane = t & 31, w = t >> 5;
    int base = t * CH;
    int h[CH];
    int s = 0;
    #pragma unroll
    for (int i = 0; i < CH; i++) {
        int j = base + i;
        h[i] = (j < N_NODES) ? g_hist[j] : 0;
        s += h[i];
    }
    int ps = s;
    #pragma unroll
    for (int o = 1; o < 32; o <<= 1) {
        int u = __shfl_up_sync(0xffffffffu, ps, o);
        if (lane >= o) ps += u;
    }
    if (lane == 31) wsum[w] = ps;
    __syncthreads();
    if (w == 0) {
        int v = wsum[lane];
        #pragma unroll
        for (int o = 1; o < 32; o <<= 1) {
            int u = __shfl_up_sync(0xffffffffu, v, o);
            if (lane >= o) v += u;
        }
        wsum[lane] = v;
    }
    __syncthreads();
    int run = ps - s + ((w > 0) ? wsum[w - 1] : 0);
    #pragma unroll
    for (int i = 0; i < CH; i++) {
        int j = base + i;
        if (j < N_NODES) { g_off[j] = run; g_cursor[j] = run; run += h[i]; }
    }
    if (t == 1023) g_off[N_NODES] = run;
}
__global__ void fill_kernel(const int* __restrict__ idx) {
    int i = blockIdx.x * blockDim.x + threadIdx.x;
    int st = gridDim.x * blockDim.x;
    for (int e = i; e < E_EDGES; e += st)
        g_elist[atomicAdd(&g_cursor[idx[e]], 1)] = e;
}

// ---- tensor-core GEMM (bf16 3-term, ldmatrix, pipelined) -> g_msg. grid (X, 3) ----
__global__ void __launch_bounds__(512, 1)
gemm_kernel(const float* __restrict__ s,
            const float* __restrict__ Wphi, const float* __restrict__ bphi,
            const float* __restrict__ Ww, const float* __restrict__ bw)
{
    extern __shared__ char sm[];
    float* bphi_s = (float*)(sm + OFF_BPHI);
    float* bw_s   = (float*)(sm + OFF_BW);

    const int tid  = threadIdx.x;
    const int wid  = tid >> 5;
    const int lane = tid & 31;
    const int mt   = wid >> 1;       // m-tile 0..7
    const int nh   = wid & 1;        // n-half
    const int group = blockIdx.y;
    const int goff  = group * 128;
    const uint32_t smb = smem_u32(sm);

    // ---- one-time weights into smem ----
    {
        __nv_bfloat16* B_hi = (__nv_bfloat16*)(sm + OFF_BHI);
        __nv_bfloat16* B_lo = (__nv_bfloat16*)(sm + OFF_BLO);
        __nv_bfloat16* Wwh  = (__nv_bfloat16*)(sm + OFF_WWH);
        __nv_bfloat16* Wwl  = (__nv_bfloat16*)(sm + OFF_WWL);
        for (int i = tid; i < 128 * 128; i += 512) {
            int n = i >> 7, k = i & 127;
            __nv_bfloat16 h, l;
            split1(Wphi[k * 384 + goff + n], h, l);
            B_hi[n * PITCH + k] = h;
            B_lo[n * PITCH + k] = l;
        }
        for (int i = tid; i < 128 * 32; i += 512) {
            int n = i >> 5, k = i & 31;
            float x = (k < N_RBF) ? Ww[k * 384 + goff + n] : 0.f;
            __nv_bfloat16 h, l;
            split1(x, h, l);
            Wwh[n * WPITCH + k] = h;
            Wwl[n * WPITCH + k] = l;
        }
        if (tid < 128) { bphi_s[tid] = bphi[goff + tid]; bw_s[tid] = bw[goff + tid]; }
    }

    // ldmatrix per-thread addresses
    const int arow = mt * 16 + (lane & 15);
    const int acol = (lane >> 4) << 3;
    const int brl  = ((lane >> 4) << 3) + (lane & 7);
    const int bk   = ((lane >> 3) & 1) << 3;

    const uint32_t aH = smb + OFF_AHI + (uint32_t)(arow * PITCH + acol) * 2;
    const uint32_t aL = smb + OFF_ALO + (uint32_t)(arow * PITCH + acol) * 2;
    const uint32_t bH = smb + OFF_BHI + (uint32_t)((nh * 64 + brl) * PITCH + bk) * 2;
    const uint32_t bL = smb + OFF_BLO + (uint32_t)((nh * 64 + brl) * PITCH + bk) * 2;
    const uint32_t rH = smb + OFF_RBH + (uint32_t)(arow * WPITCH + acol) * 2;
    const uint32_t rL = smb + OFF_RBL + (uint32_t)(arow * WPITCH + acol) * 2;
    const uint32_t wH = smb + OFF_WWH + (uint32_t)((nh * 64 + brl) * WPITCH + bk) * 2;
    const uint32_t wL = smb + OFF_WWL + (uint32_t)((nh * 64 + brl) * WPITCH + bk) * 2;

    const int eL   = tid >> 2;          // staging: edge row
    const int cbL  = (tid & 3) * 32;    // staging: col base
    const int rrow = tid >> 2;          // rbf staging row
    const int rseg = tid & 3;
    const int ep0  = mt * 16 + (lane >> 2);  // epilogue rows
    const int ep1  = ep0 + 8;
    const int t4   = lane & 3;

    // ---- prologue: prefetch tile 0 into registers ----
    float4 st4[8];
    uint4  rh, rl;
    {
        const int eb0 = blockIdx.x * TILE_E;
        const float* p = &s[(size_t)(eb0 + eL) * 128 + cbL];
        #pragma unroll
        for (int q = 0; q < 8; q++) st4[q] = __ldg((const float4*)p + q);
        rh = __ldg((const uint4*)&g_rbfh[(size_t)(eb0 + rrow) * 32] + rseg);
        rl = __ldg((const uint4*)&g_rbfl[(size_t)(eb0 + rrow) * 32] + rseg);
    }
    __syncthreads();   // weights ready

    for (int tile = blockIdx.x; tile < NTILES; tile += gridDim.x) {
        const int ebase = tile * TILE_E;

        // ---- stage: registers -> smem (split A, rbf) ----
        {
            __nv_bfloat16* A_hi = (__nv_bfloat16*)(sm + OFF_AHI);
            __nv_bfloat16* A_lo = (__nv_bfloat16*)(sm + OFF_ALO);
            #pragma unroll
            for (int b = 0; b < 8; b++) {
                uint2 hi, lo;
                split2(st4[b].x, st4[b].y, hi.x, lo.x);
                split2(st4[b].z, st4[b].w, hi.y, lo.y);
                int o = eL * PITCH + cbL + b * 4;
                *(uint2*)&A_hi[o] = hi;
                *(uint2*)&A_lo[o] = lo;
            }
            __nv_bfloat16* Rbh = (__nv_bfloat16*)(sm + OFF_RBH);
            __nv_bfloat16* Rbl = (__nv_bfloat16*)(sm + OFF_RBL);
            *(uint4*)&Rbh[rrow * WPITCH + rseg * 8] = rh;
            *(uint4*)&Rbl[rrow * WPITCH + rseg * 8] = rl;
        }
        __syncthreads();

        // ---- prefetch next tile (overlaps all MMA work below) ----
        {
            int nt = tile + gridDim.x; if (nt >= NTILES) nt = tile;
            const int ebn = nt * TILE_E;
            const float* p = &s[(size_t)(ebn + eL) * 128 + cbL];
            #pragma unroll
            for (int q = 0; q < 8; q++) st4[q] = __ldg((const float4*)p + q);
            rh = __ldg((const uint4*)&g_rbfh[(size_t)(ebn + rrow) * 32] + rseg);
            rl = __ldg((const uint4*)&g_rbfl[(size_t)(ebn + rrow) * 32] + rseg);
        }

        // ---- w-GEMM: acc_w = rbf @ Ww (3-term, K=32) ----
        float acc_w[8][4];
        #pragma unroll
        for (int j = 0; j < 8; j++)
            acc_w[j][0] = acc_w[j][1] = acc_w[j][2] = acc_w[j][3] = 0.f;
        #pragma unroll
        for (int kk = 0; kk < 2; kk++) {
            const uint32_t ko = kk * 32;
            uint32_t ah0, ah1, ah2, ah3, al0, al1, al2, al3;
            ldsm4(ah0, ah1, ah2, ah3, rH + ko);
            ldsm4(al0, al1, al2, al3, rL + ko);
            #pragma unroll
            for (int jj = 0; jj < 4; jj++) {
                const uint32_t bo = (uint32_t)(jj * 16 * WPITCH) * 2 + ko;
                uint32_t bh0, bh1, bh2, bh3, bl0, bl1, bl2, bl3;
                ldsm4(bh0, bh1, bh2, bh3, wH + bo);
                ldsm4(bl0, bl1, bl2, bl3, wL + bo);
                mma_bf16(acc_w[2*jj],   ah0, ah1, ah2, ah3, bh0, bh1);
                mma_bf16(acc_w[2*jj],   ah0, ah1, ah2, ah3, bl0, bl1);
                mma_bf16(acc_w[2*jj],   al0, al1, al2, al3, bh0, bh1);
                mma_bf16(acc_w[2*jj+1], ah0, ah1, ah2, ah3, bh2, bh3);
                mma_bf16(acc_w[2*jj+1], ah0, ah1, ah2, ah3, bl2, bl3);
                mma_bf16(acc_w[2*jj+1], al0, al1, al2, al3, bh2, bh3);
            }
        }

        // ---- main GEMM: acc = s @ Wphi (3-term, K=128) ----
        float acc[8][4];
        #pragma unroll
        for (int j = 0; j < 8; j++)
            acc[j][0] = acc[j][1] = acc[j][2] = acc[j][3] = 0.f;
        #pragma unroll 1
        for (int kk = 0; kk < 8; kk++) {
            const uint32_t ko = kk * 32;
            uint32_t ah0, ah1, ah2, ah3, al0, al1, al2, al3;
            ldsm4(ah0, ah1, ah2, ah3, aH + ko);
            ldsm4(al0, al1, al2, al3, aL + ko);
            #pragma unroll
            for (int jj = 0; jj < 4; jj++) {
                const uint32_t bo = (uint32_t)(jj * 16 * PITCH) * 2 + ko;
                uint32_t bh0, bh1, bh2, bh3, bl0, bl1, bl2, bl3;
                ldsm4(bh0, bh1, bh2, bh3, bH + bo);
                ldsm4(bl0, bl1, bl2, bl3, bL + bo);
                mma_bf16(acc[2*jj],   ah0, ah1, ah2, ah3, bh0, bh1);
                mma_bf16(acc[2*jj],   ah0, ah1, ah2, ah3, bl0, bl1);
                mma_bf16(acc[2*jj],   al0, al1, al2, al3, bh0, bh1);
                mma_bf16(acc[2*jj+1], ah0, ah1, ah2, ah3, bh2, bh3);
                mma_bf16(acc[2*jj+1], ah0, ah1, ah2, ah3, bl2, bl3);
                mma_bf16(acc[2*jj+1], al0, al1, al2, al3, bh2, bh3);
            }
        }
        __syncthreads();   // all ldmatrix reads done before next iter's STS

        // ---- epilogue: sp = (acc_w + bw) * (acc + bphi) -> direct STG.64 ----
        {
            float* row0 = &g_msg[(size_t)(ebase + ep0) * 384 + goff];
            float* row1 = &g_msg[(size_t)(ebase + ep1) * 384 + goff];
            #pragma unroll
            for (int j = 0; j < 8; j++) {
                int cj = nh * 64 + j * 8 + t4 * 2;
                ull bp  = *(ull*)&bphi_s[cj];
                ull bwj = *(ull*)&bw_s[cj];
                ull w0 = add2(pack2(acc_w[j][0], acc_w[j][1]), bwj);
                ull w1 = add2(pack2(acc_w[j][2], acc_w[j][3]), bwj);
                ull p0 = mul2(w0, add2(pack2(acc[j][0], acc[j][1]), bp));
                ull p1 = mul2(w1, add2(pack2(acc[j][2], acc[j][3]), bp));
                *(ull*)(row0 + cj) = p0;
                *(ull*)(row1 + cj) = p1;
            }
        }
    }
}

// ---- per-node gather ----
__global__ void __launch_bounds__(128)
gather_kernel(const float* __restrict__ r, const float* __restrict__ v,
              float* __restrict__ out)
{
    const int n = blockIdx.x;
    const int f = threadIdx.x;
    const float ginv = (float)(1.0 / sqrt(g_sumsq));
    const int beg = g_off[n], end = g_off[n + 1];

    float a0 = 0.f, a1 = 0.f, a2 = 0.f, as = 0.f;
    int p = beg;
    #pragma unroll 1
    for (; p + 2 <= end; p += 2) {
        const int ea = g_elist[p], eb = g_elist[p + 1];
        const float* ma = &g_msg[(size_t)ea * 384];
        const float* mb = &g_msg[(size_t)eb * 384];
        const float* va = &v[(size_t)ea * 384];
        const float* vb = &v[(size_t)eb * 384];
        float s0a = ma[f], s1a = ma[128 + f], s2a = ma[256 + f];
        float s0b = mb[f], s1b = mb[128 + f], s2b = mb[256 + f];
        float va0 = va[f], va1 = va[128 + f], va2 = va[256 + f];
        float vb0 = vb[f], vb1 = vb[128 + f], vb2 = vb[256 + f];
        float ra0 = __ldg(&r[ea * 3]), ra1 = __ldg(&r[ea * 3 + 1]), ra2 = __ldg(&r[ea * 3 + 2]);
        float rb0 = __ldg(&r[eb * 3]), rb1 = __ldg(&r[eb * 3 + 1]), rb2 = __ldg(&r[eb * 3 + 2]);
        a0 += s2a * (ra0 * ginv) + s0a * va0 + s2b * (rb0 * ginv) + s0b * vb0;
        a1 += s2a * (ra1 * ginv) + s0a * va1 + s2b * (rb1 * ginv) + s0b * vb1;
        a2 += s2a * (ra2 * ginv) + s0a * va2 + s2b * (rb2 * ginv) + s0b * vb2;
        as += s1a + s1b;
    }
    if (p < end) {
        const int e = g_elist[p];
        const float* m  = &g_msg[(size_t)e * 384];
        const float* vp = &v[(size_t)e * 384];
        float sp0 = m[f], sp1 = m[128 + f], sp2 = m[256 + f];
        float r0 = __ldg(&r[e * 3]), r1 = __ldg(&r[e * 3 + 1]), r2 = __ldg(&r[e * 3 + 2]);
        a0 += sp2 * (r0 * ginv) + sp0 * vp[f];
        a1 += sp2 * (r1 * ginv) + sp0 * vp[128 + f];
        a2 += sp2 * (r2 * ginv) + sp0 * vp[256 + f];
        as += sp1;
    }
    size_t ob = (size_t)n * 384;
    out[ob + f]       = a0;
    out[ob + 128 + f] = a1;
    out[ob + 256 + f] = a2;
    out[OUT_S_OFF + (size_t)n * 128 + f] = as;
}

extern "C" void kernel_launch(void* const* d_in, const int* in_sizes, int n_in,
                              void* d_out, int out_size) {
    const float* s    = (const float*)d_in[0];
    const float* r    = (const float*)d_in[1];
    const float* v    = (const float*)d_in[2];
    const int*   idx  = (const int*)d_in[3];
    const float* Wphi = (const float*)d_in[4];
    const float* bphi = (const float*)d_in[5];
    const float* Ww   = (const float*)d_in[6];
    const float* bw   = (const float*)d_in[7];
    float* out = (float*)d_out;

    static cudaStream_t s2 = nullptr;
    static cudaEvent_t evFork = nullptr, evJoin = nullptr;
    if (s2 == nullptr) {
        cudaStreamCreateWithFlags(&s2, cudaStreamNonBlocking);
        cudaEventCreateWithFlags(&evFork, cudaEventDisableTiming);
        cudaEventCreateWithFlags(&evJoin, cudaEventDisableTiming);
    }

    cudaEventRecord(evFork, 0);
    cudaStreamWaitEvent(s2, evFork, 0);

    reset_kernel<<<64, 256, 0, s2>>>();
    hist_sumsq_kernel<<<256, 256, 0, s2>>>(idx, r);
    scan_kernel<<<1, 1024, 0, s2>>>();
    fill_kernel<<<256, 256, 0, s2>>>(idx);
    cudaEventRecord(evJoin, s2);

    rbf_kernel<<<2048, 256>>>(r);

    cudaFuncSetAttribute(gemm_kernel,
                         cudaFuncAttributeMaxDynamicSharedMemorySize, SMEM_SZ);
    gemm_kernel<<<dim3(148, 3), 512, SMEM_SZ>>>(s, Wphi, bphi, Ww, bw);

    cudaStreamWaitEvent(0, evJoin, 0);
    gather_kernel<<<N_NODES, 128>>>(r, v, out);
}

// round 9
// speedup vs baseline: 1.4725x; 1.1354x over previous
#include <cuda_runtime.h>
#include <cuda_fp16.h>
#include <cstdint>
#include <cstddef>

#define E_EDGES 320000
#define N_NODES 20000
#define N_RBF   20
#define TILE_E  128
#define NTILES  2500
#define OUT_S_OFF ((size_t)N_NODES * 3 * 128)
#define PITCH   136     // fp16/row, A & B tiles (conflict-free ldmatrix)
#define WPITCH  40      // fp16/row, rbf & Ww tiles (K padded to 32)

typedef unsigned long long ull;

// ---- device scratch ----
__device__ float   g_msg[(size_t)E_EDGES * 384];
__device__ __half  g_rbf[(size_t)E_EDGES * 32];
__device__ int     g_hist[N_NODES];
__device__ int     g_cursor[N_NODES];
__device__ int     g_off[N_NODES + 1];
__device__ int     g_elist[E_EDGES];
__device__ double  g_sumsq;

// ---- f32x2 helpers ----
__device__ __forceinline__ ull pack2(float lo, float hi) {
    ull r; asm("mov.b64 %0, {%1,%2};" : "=l"(r) : "f"(lo), "f"(hi)); return r;
}
__device__ __forceinline__ ull mul2(ull a, ull b) {
    ull d; asm("mul.rn.f32x2 %0, %1, %2;" : "=l"(d) : "l"(a), "l"(b)); return d;
}
__device__ __forceinline__ ull add2(ull a, ull b) {
    ull d; asm("add.rn.f32x2 %0, %1, %2;" : "=l"(d) : "l"(a), "l"(b)); return d;
}

// ---- tensor-core primitives (baseline PTX) ----
__device__ __forceinline__ void mma_f16(float* d, uint32_t a0, uint32_t a1,
                                        uint32_t a2, uint32_t a3,
                                        uint32_t b0, uint32_t b1) {
    asm volatile(
        "mma.sync.aligned.m16n8k16.row.col.f32.f16.f16.f32 "
        "{%0,%1,%2,%3}, {%4,%5,%6,%7}, {%8,%9}, {%0,%1,%2,%3};"
        : "+f"(d[0]), "+f"(d[1]), "+f"(d[2]), "+f"(d[3])
        : "r"(a0), "r"(a1), "r"(a2), "r"(a3), "r"(b0), "r"(b1));
}
__device__ __forceinline__ void ldsm4(uint32_t& r0, uint32_t& r1,
                                      uint32_t& r2, uint32_t& r3, uint32_t a) {
    asm volatile("ldmatrix.sync.aligned.m8n8.x4.shared.b16 {%0,%1,%2,%3}, [%4];"
                 : "=r"(r0), "=r"(r1), "=r"(r2), "=r"(r3) : "r"(a));
}
__device__ __forceinline__ uint32_t smem_u32(const void* p) {
    uint32_t a;
    asm("{ .reg .u64 t; cvta.to.shared.u64 t, %1; cvt.u32.u64 %0, t; }"
        : "=r"(a) : "l"(p));
    return a;
}
__device__ __forceinline__ void split1h(float x, __half& h, __half& l) {
    h = __float2half_rn(x);
    l = __float2half_rn(x - __half2float(h));
}

// smem byte offsets
#define OFF_A0   0                // 128*136*2 = 34816 (fp16 A, buffer 0)
#define OFF_A1   34816            // buffer 1
#define OFF_BHI  69632
#define OFF_BLO  104448
#define OFF_WWH  139264           // 128*40*2 = 10240
#define OFF_WWL  149504
#define OFF_RB0  159744           // rbf fp16, buffer 0 (10240)
#define OFF_RB1  169984           // buffer 1
#define OFF_BPHI 180224
#define OFF_BW   180736
#define SMEM_SZ  181248

// ---- rbf precompute (single fp16) ----
__global__ void rbf_kernel(const float* __restrict__ r) {
    int i = blockIdx.x * blockDim.x + threadIdx.x;
    int st = gridDim.x * blockDim.x;
    for (; i < E_EDGES * 32; i += st) {
        int e = i >> 5, n = i & 31;
        float x = 0.f;
        if (n < N_RBF) {
            float rx = __ldg(&r[e * 3]);
            float ry = __ldg(&r[e * 3 + 1]);
            float rz = __ldg(&r[e * 3 + 2]);
            float rn = sqrtf(rx * rx + ry * ry + rz * rz);
            float tt = sinf((float)(n + 1) * (3.14159265358979323846f / 5.0f) * rn) / rn;
            x = (tt <= 5.0f)
                ? 0.5f * (cosf(3.14159265358979323846f * 0.2f * tt) + 1.0f) : 0.0f;
        }
        g_rbf[i] = __float2half_rn(x);
    }
}

// ---- CSR/misc kernels ----
__global__ void reset_kernel() {
    int i = blockIdx.x * blockDim.x + threadIdx.x;
    if (i == 0) g_sumsq = 0.0;
    int st = gridDim.x * blockDim.x;
    for (int j = i; j < N_NODES; j += st) g_hist[j] = 0;
}
__global__ void hist_sumsq_kernel(const int* __restrict__ idx,
                                  const float* __restrict__ r) {
    int i = blockIdx.x * blockDim.x + threadIdx.x;
    int st = gridDim.x * blockDim.x;
    for (int e = i; e < E_EDGES; e += st) atomicAdd(&g_hist[idx[e]], 1);
    float s = 0.f;
    for (int j = i; j < E_EDGES * 3; j += st) { float x = r[j]; s += x * x; }
    #pragma unroll
    for (int o = 16; o > 0; o >>= 1) s += __shfl_down_sync(0xffffffffu, s, o);
    __shared__ float ws[8];
    if ((threadIdx.x & 31) == 0) ws[threadIdx.x >> 5] = s;
    __syncthreads();
    if (threadIdx.x < 8) {
        float t = ws[threadIdx.x];
        #pragma unroll
        for (int o = 4; o > 0; o >>= 1) t += __shfl_down_sync(0xffu, t, o);
        if (threadIdx.x == 0) atomicAdd(&g_sumsq, (double)t);
    }
}
__global__ void __launch_bounds__(1024) scan_kernel() {
    const int CH = 20;
    __shared__ int wsum[32];
    int t = threadIdx.x, lane = t & 31, w = t >> 5;
    int base = t * CH;
    int h[CH];
    int s = 0;
    #pragma unroll
    for (int i = 0; i < CH; i++) {
        int j = base + i;
        h[i] = (j < N_NODES) ? g_hist[j] : 0;
        s += h[i];
    }
    int ps = s;
    #pragma unroll
    for (int o = 1; o < 32; o <<= 1) {
        int u = __shfl_up_sync(0xffffffffu, ps, o);
        if (lane >= o) ps += u;
    }
    if (lane == 31) wsum[w] = ps;
    __syncthreads();
    if (w == 0) {
        int v = wsum[lane];
        #pragma unroll
        for (int o = 1; o < 32; o <<= 1) {
            int u = __shfl_up_sync(0xffffffffu, v, o);
            if (lane >= o) v += u;
        }
        wsum[lane] = v;
    }
    __syncthreads();
    int run = ps - s + ((w > 0) ? wsum[w - 1] : 0);
    #pragma unroll
    for (int i = 0; i < CH; i++) {
        int j = base + i;
        if (j < N_NODES) { g_off[j] = run; g_cursor[j] = run; run += h[i]; }
    }
    if (t == 1023) g_off[N_NODES] = run;
}
__global__ void fill_kernel(const int* __restrict__ idx) {
    int i = blockIdx.x * blockDim.x + threadIdx.x;
    int st = gridDim.x * blockDim.x;
    for (int e = i; e < E_EDGES; e += st)
        g_elist[atomicAdd(&g_cursor[idx[e]], 1)] = e;
}

// ---- tensor-core GEMM (fp16 2-term, ldmatrix, double-buffered) ----
// grid (X, 3): blockIdx.y = column group
__global__ void __launch_bounds__(512, 1)
gemm_kernel(const float* __restrict__ s,
            const float* __restrict__ Wphi, const float* __restrict__ bphi,
            const float* __restrict__ Ww, const float* __restrict__ bw)
{
    extern __shared__ char sm[];
    float* bphi_s = (float*)(sm + OFF_BPHI);
    float* bw_s   = (float*)(sm + OFF_BW);

    const int tid  = threadIdx.x;
    const int wid  = tid >> 5;
    const int lane = tid & 31;
    const int mt   = wid >> 1;       // m-tile 0..7
    const int nh   = wid & 1;        // n-half
    const int group = blockIdx.y;
    const int goff  = group * 128;
    const uint32_t smb = smem_u32(sm);

    // ---- one-time weights into smem (fp16 hi/lo) ----
    {
        __half* B_hi = (__half*)(sm + OFF_BHI);
        __half* B_lo = (__half*)(sm + OFF_BLO);
        __half* Wwh  = (__half*)(sm + OFF_WWH);
        __half* Wwl  = (__half*)(sm + OFF_WWL);
        for (int i = tid; i < 128 * 128; i += 512) {
            int n = i >> 7, k = i & 127;
            __half h, l;
            split1h(Wphi[k * 384 + goff + n], h, l);
            B_hi[n * PITCH + k] = h;
            B_lo[n * PITCH + k] = l;
        }
        for (int i = tid; i < 128 * 32; i += 512) {
            int n = i >> 5, k = i & 31;
            float x = (k < N_RBF) ? Ww[k * 384 + goff + n] : 0.f;
            __half h, l;
            split1h(x, h, l);
            Wwh[n * WPITCH + k] = h;
            Wwl[n * WPITCH + k] = l;
        }
        if (tid < 128) { bphi_s[tid] = bphi[goff + tid]; bw_s[tid] = bw[goff + tid]; }
    }

    // ldmatrix per-thread address components
    const int arow = mt * 16 + (lane & 15);
    const int acol = (lane >> 4) << 3;
    const int brl  = ((lane >> 4) << 3) + (lane & 7);
    const int bk   = ((lane >> 3) & 1) << 3;

    const uint32_t aOff = (uint32_t)(arow * PITCH + acol) * 2;     // within A buffer
    const uint32_t rOff = (uint32_t)(arow * WPITCH + acol) * 2;    // within rbf buffer
    const uint32_t bH = smb + OFF_BHI + (uint32_t)((nh * 64 + brl) * PITCH + bk) * 2;
    const uint32_t bL = smb + OFF_BLO + (uint32_t)((nh * 64 + brl) * PITCH + bk) * 2;
    const uint32_t wH = smb + OFF_WWH + (uint32_t)((nh * 64 + brl) * WPITCH + bk) * 2;
    const uint32_t wL = smb + OFF_WWL + (uint32_t)((nh * 64 + brl) * WPITCH + bk) * 2;

    const int eL   = tid >> 2;          // staging: edge row
    const int cbL  = (tid & 3) * 32;    // staging: col base
    const int rrow = tid >> 2;          // rbf staging row
    const int rseg = tid & 3;
    const int ep0  = mt * 16 + (lane >> 2);  // epilogue rows
    const int ep1  = ep0 + 8;
    const int t4   = lane & 3;

    // ---- prologue: prefetch tile 0, stage into buffer 0 ----
    float4 st4[8];
    uint4  rhv;
    {
        const int eb0 = blockIdx.x * TILE_E;
        const float* p = &s[(size_t)(eb0 + eL) * 128 + cbL];
        #pragma unroll
        for (int q = 0; q < 8; q++) st4[q] = __ldg((const float4*)p + q);
        rhv = __ldg((const uint4*)&g_rbf[(size_t)(eb0 + rrow) * 32] + rseg);
    }
    {
        __half* A0 = (__half*)(sm + OFF_A0);
        #pragma unroll
        for (int b = 0; b < 8; b++) {
            __half2 h01 = __floats2half2_rn(st4[b].x, st4[b].y);
            __half2 h23 = __floats2half2_rn(st4[b].z, st4[b].w);
            uint2 u;
            u.x = *reinterpret_cast<uint32_t*>(&h01);
            u.y = *reinterpret_cast<uint32_t*>(&h23);
            *(uint2*)&A0[eL * PITCH + cbL + b * 4] = u;
        }
        __half* R0 = (__half*)(sm + OFF_RB0);
        *(uint4*)&R0[rrow * WPITCH + rseg * 8] = rhv;
    }
    __syncthreads();

    uint32_t par = 0;
    for (int tile = blockIdx.x; tile < NTILES; tile += gridDim.x) {
        const int ebase = tile * TILE_E;
        const uint32_t aCur = smb + (par ? OFF_A1 : OFF_A0) + aOff;
        const uint32_t rCur = smb + (par ? OFF_RB1 : OFF_RB0) + rOff;

        // ---- prefetch next tile (LDG latency hidden by MMAs) ----
        {
            int nt = tile + gridDim.x; if (nt >= NTILES) nt = tile;
            const int ebn = nt * TILE_E;
            const float* p = &s[(size_t)(ebn + eL) * 128 + cbL];
            #pragma unroll
            for (int q = 0; q < 8; q++) st4[q] = __ldg((const float4*)p + q);
            rhv = __ldg((const uint4*)&g_rbf[(size_t)(ebn + rrow) * 32] + rseg);
        }

        // ---- w-GEMM: acc_w = rbf(fp16) @ (Wwh + Wwl), K=32 ----
        float acc_w[8][4];
        #pragma unroll
        for (int j = 0; j < 8; j++)
            acc_w[j][0] = acc_w[j][1] = acc_w[j][2] = acc_w[j][3] = 0.f;
        #pragma unroll
        for (int kk = 0; kk < 2; kk++) {
            const uint32_t ko = kk * 32;
            uint32_t a0, a1, a2, a3;
            ldsm4(a0, a1, a2, a3, rCur + ko);
            #pragma unroll
            for (int jj = 0; jj < 4; jj++) {
                const uint32_t bo = (uint32_t)(jj * 16 * WPITCH) * 2 + ko;
                uint32_t h0, h1, h2, h3, l0, l1, l2, l3;
                ldsm4(h0, h1, h2, h3, wH + bo);
                ldsm4(l0, l1, l2, l3, wL + bo);
                mma_f16(acc_w[2*jj],   a0, a1, a2, a3, h0, h1);
                mma_f16(acc_w[2*jj],   a0, a1, a2, a3, l0, l1);
                mma_f16(acc_w[2*jj+1], a0, a1, a2, a3, h2, h3);
                mma_f16(acc_w[2*jj+1], a0, a1, a2, a3, l2, l3);
            }
        }

        // ---- main GEMM: acc = s(fp16) @ (Bhi + Blo), K=128 ----
        float acc[8][4];
        #pragma unroll
        for (int j = 0; j < 8; j++)
            acc[j][0] = acc[j][1] = acc[j][2] = acc[j][3] = 0.f;
        #pragma unroll 1
        for (int kk = 0; kk < 8; kk++) {
            const uint32_t ko = kk * 32;
            uint32_t a0, a1, a2, a3;
            ldsm4(a0, a1, a2, a3, aCur + ko);
            #pragma unroll
            for (int jj = 0; jj < 4; jj++) {
                const uint32_t bo = (uint32_t)(jj * 16 * PITCH) * 2 + ko;
                uint32_t h0, h1, h2, h3, l0, l1, l2, l3;
                ldsm4(h0, h1, h2, h3, bH + bo);
                ldsm4(l0, l1, l2, l3, bL + bo);
                mma_f16(acc[2*jj],   a0, a1, a2, a3, h0, h1);
                mma_f16(acc[2*jj],   a0, a1, a2, a3, l0, l1);
                mma_f16(acc[2*jj+1], a0, a1, a2, a3, h2, h3);
                mma_f16(acc[2*jj+1], a0, a1, a2, a3, l2, l3);
            }
        }

        // ---- epilogue: sp = (acc_w + bw) * (acc + bphi) -> direct STG.64 ----
        {
            float* row0 = &g_msg[(size_t)(ebase + ep0) * 384 + goff];
            float* row1 = &g_msg[(size_t)(ebase + ep1) * 384 + goff];
            #pragma unroll
            for (int j = 0; j < 8; j++) {
                int cj = nh * 64 + j * 8 + t4 * 2;
                ull bp  = *(ull*)&bphi_s[cj];
                ull bwj = *(ull*)&bw_s[cj];
                ull w0 = add2(pack2(acc_w[j][0], acc_w[j][1]), bwj);
                ull w1 = add2(pack2(acc_w[j][2], acc_w[j][3]), bwj);
                ull p0 = mul2(w0, add2(pack2(acc[j][0], acc[j][1]), bp));
                ull p1 = mul2(w1, add2(pack2(acc[j][2], acc[j][3]), bp));
                *(ull*)(row0 + cj) = p0;
                *(ull*)(row1 + cj) = p1;
            }
        }

        // ---- stage next tile into the OTHER buffer (no conflict with cur) ----
        {
            __half* An = (__half*)(sm + (par ? OFF_A0 : OFF_A1));
            #pragma unroll
            for (int b = 0; b < 8; b++) {
                __half2 h01 = __floats2half2_rn(st4[b].x, st4[b].y);
                __half2 h23 = __floats2half2_rn(st4[b].z, st4[b].w);
                uint2 u;
                u.x = *reinterpret_cast<uint32_t*>(&h01);
                u.y = *reinterpret_cast<uint32_t*>(&h23);
                *(uint2*)&An[eL * PITCH + cbL + b * 4] = u;
            }
            __half* Rn = (__half*)(sm + (par ? OFF_RB0 : OFF_RB1));
            *(uint4*)&Rn[rrow * WPITCH + rseg * 8] = rhv;
        }
        __syncthreads();   // next buffer staged; flip
        par ^= 1;
    }
}

// ---- per-node gather ----
__global__ void __launch_bounds__(128)
gather_kernel(const float* __restrict__ r, const float* __restrict__ v,
              float* __restrict__ out)
{
    const int n = blockIdx.x;
    const int f = threadIdx.x;
    const float ginv = (float)(1.0 / sqrt(g_sumsq));
    const int beg = g_off[n], end = g_off[n + 1];

    float a0 = 0.f, a1 = 0.f, a2 = 0.f, as = 0.f;
    int p = beg;
    #pragma unroll 1
    for (; p + 2 <= end; p += 2) {
        const int ea = g_elist[p], eb = g_elist[p + 1];
        const float* ma = &g_msg[(size_t)ea * 384];
        const float* mb = &g_msg[(size_t)eb * 384];
        const float* va = &v[(size_t)ea * 384];
        const float* vb = &v[(size_t)eb * 384];
        float s0a = ma[f], s1a = ma[128 + f], s2a = ma[256 + f];
        float s0b = mb[f], s1b = mb[128 + f], s2b = mb[256 + f];
        float va0 = va[f], va1 = va[128 + f], va2 = va[256 + f];
        float vb0 = vb[f], vb1 = vb[128 + f], vb2 = vb[256 + f];
        float ra0 = __ldg(&r[ea * 3]), ra1 = __ldg(&r[ea * 3 + 1]), ra2 = __ldg(&r[ea * 3 + 2]);
        float rb0 = __ldg(&r[eb * 3]), rb1 = __ldg(&r[eb * 3 + 1]), rb2 = __ldg(&r[eb * 3 + 2]);
        a0 += s2a * (ra0 * ginv) + s0a * va0 + s2b * (rb0 * ginv) + s0b * vb0;
        a1 += s2a * (ra1 * ginv) + s0a * va1 + s2b * (rb1 * ginv) + s0b * vb1;
        a2 += s2a * (ra2 * ginv) + s0a * va2 + s2b * (rb2 * ginv) + s0b * vb2;
        as += s1a + s1b;
    }
    if (p < end) {
        const int e = g_elist[p];
        const float* m  = &g_msg[(size_t)e * 384];
        const float* vp = &v[(size_t)e * 384];
        float sp0 = m[f], sp1 = m[128 + f], sp2 = m[256 + f];
        float r0 = __ldg(&r[e * 3]), r1 = __ldg(&r[e * 3 + 1]), r2 = __ldg(&r[e * 3 + 2]);
        a0 += sp2 * (r0 * ginv) + sp0 * vp[f];
        a1 += sp2 * (r1 * ginv) + sp0 * vp[128 + f];
        a2 += sp2 * (r2 * ginv) + sp0 * vp[256 + f];
        as += sp1;
    }
    size_t ob = (size_t)n * 384;
    out[ob + f]       = a0;
    out[ob + 128 + f] = a1;
    out[ob + 256 + f] = a2;
    out[OUT_S_OFF + (size_t)n * 128 + f] = as;
}

extern "C" void kernel_launch(void* const* d_in, const int* in_sizes, int n_in,
                              void* d_out, int out_size) {
    const float* s    = (const float*)d_in[0];
    const float* r    = (const float*)d_in[1];
    const float* v    = (const float*)d_in[2];
    const int*   idx  = (const int*)d_in[3];
    const float* Wphi = (const float*)d_in[4];
    const float* bphi = (const float*)d_in[5];
    const float* Ww   = (const float*)d_in[6];
    const float* bw   = (const float*)d_in[7];
    float* out = (float*)d_out;

    static cudaStream_t s2 = nullptr;
    static cudaEvent_t evFork = nullptr, evJoin = nullptr;
    if (s2 == nullptr) {
        cudaStreamCreateWithFlags(&s2, cudaStreamNonBlocking);
        cudaEventCreateWithFlags(&evFork, cudaEventDisableTiming);
        cudaEventCreateWithFlags(&evJoin, cudaEventDisableTiming);
    }

    cudaEventRecord(evFork, 0);
    cudaStreamWaitEvent(s2, evFork, 0);

    reset_kernel<<<64, 256, 0, s2>>>();
    hist_sumsq_kernel<<<256, 256, 0, s2>>>(idx, r);
    scan_kernel<<<1, 1024, 0, s2>>>();
    fill_kernel<<<256, 256, 0, s2>>>(idx);
    cudaEventRecord(evJoin, s2);

    rbf_kernel<<<2048, 256>>>(r);

    cudaFuncSetAttribute(gemm_kernel,
                         cudaFuncAttributeMaxDynamicSharedMemorySize, SMEM_SZ);
    gemm_kernel<<<dim3(148, 3), 512, SMEM_SZ>>>(s, Wphi, bphi, Ww, bw);

    cudaStreamWaitEvent(0, evJoin, 0);
    gather_kernel<<<N_NODES, 128>>>(r, v, out);
}

// round 10
// speedup vs baseline: 1.6793x; 1.1404x over previous
#include <cuda_runtime.h>
#include <cuda_fp16.h>
#include <cstdint>
#include <cstddef>

#define E_EDGES 320000
#define N_NODES 20000
#define N_RBF   20
#define TILE_E  128
#define NTILES  2500
#define OUT_S_OFF ((size_t)N_NODES * 3 * 128)
#define PITCH   136     // fp16/row, A & B tiles (conflict-free ldmatrix)
#define WPITCH  40      // fp16/row, rbf & Ww tiles (K padded to 32)

typedef unsigned long long ull;

// ---- device scratch ----
__device__ __half  g_msg[(size_t)E_EDGES * 384];   // per-edge sp, fp16
__device__ __half  g_rbf[(size_t)E_EDGES * 32];
__device__ int     g_hist[N_NODES];
__device__ int     g_cursor[N_NODES];
__device__ int     g_off[N_NODES + 1];
__device__ int     g_elist[E_EDGES];
__device__ double  g_sumsq;

// ---- f32x2 helpers ----
__device__ __forceinline__ ull pack2(float lo, float hi) {
    ull r; asm("mov.b64 %0, {%1,%2};" : "=l"(r) : "f"(lo), "f"(hi)); return r;
}
__device__ __forceinline__ float2 unpack2(ull v) {
    float2 f; asm("mov.b64 {%0,%1}, %2;" : "=f"(f.x), "=f"(f.y) : "l"(v)); return f;
}
__device__ __forceinline__ ull mul2(ull a, ull b) {
    ull d; asm("mul.rn.f32x2 %0, %1, %2;" : "=l"(d) : "l"(a), "l"(b)); return d;
}
__device__ __forceinline__ ull add2(ull a, ull b) {
    ull d; asm("add.rn.f32x2 %0, %1, %2;" : "=l"(d) : "l"(a), "l"(b)); return d;
}

// ---- tensor-core primitives (baseline PTX) ----
__device__ __forceinline__ void mma_f16(float* d, uint32_t a0, uint32_t a1,
                                        uint32_t a2, uint32_t a3,
                                        uint32_t b0, uint32_t b1) {
    asm volatile(
        "mma.sync.aligned.m16n8k16.row.col.f32.f16.f16.f32 "
        "{%0,%1,%2,%3}, {%4,%5,%6,%7}, {%8,%9}, {%0,%1,%2,%3};"
        : "+f"(d[0]), "+f"(d[1]), "+f"(d[2]), "+f"(d[3])
        : "r"(a0), "r"(a1), "r"(a2), "r"(a3), "r"(b0), "r"(b1));
}
__device__ __forceinline__ void ldsm4(uint32_t& r0, uint32_t& r1,
                                      uint32_t& r2, uint32_t& r3, uint32_t a) {
    asm volatile("ldmatrix.sync.aligned.m8n8.x4.shared.b16 {%0,%1,%2,%3}, [%4];"
                 : "=r"(r0), "=r"(r1), "=r"(r2), "=r"(r3) : "r"(a));
}
__device__ __forceinline__ uint32_t smem_u32(const void* p) {
    uint32_t a;
    asm("{ .reg .u64 t; cvta.to.shared.u64 t, %1; cvt.u32.u64 %0, t; }"
        : "=r"(a) : "l"(p));
    return a;
}
__device__ __forceinline__ void split1h(float x, __half& h, __half& l) {
    h = __float2half_rn(x);
    l = __float2half_rn(x - __half2float(h));
}

// smem byte offsets
#define OFF_A0   0                // 128*136*2 = 34816 (fp16 A, buffer 0)
#define OFF_A1   34816            // buffer 1
#define OFF_B    69632            // single fp16 Wphi slice (34816)
#define OFF_WWH  104448           // 128*40*2 = 10240
#define OFF_WWL  114688
#define OFF_RB0  124928           // rbf fp16 buffer 0 (10240)
#define OFF_RB1  135168
#define OFF_BPHI 145408           // fp32 128
#define OFF_BW   145920
#define SMEM_SZ  146432

// ---- rbf precompute (single fp16) ----
__global__ void rbf_kernel(const float* __restrict__ r) {
    int i = blockIdx.x * blockDim.x + threadIdx.x;
    int st = gridDim.x * blockDim.x;
    for (; i < E_EDGES * 32; i += st) {
        int e = i >> 5, n = i & 31;
        float x = 0.f;
        if (n < N_RBF) {
            float rx = __ldg(&r[e * 3]);
            float ry = __ldg(&r[e * 3 + 1]);
            float rz = __ldg(&r[e * 3 + 2]);
            float rn = sqrtf(rx * rx + ry * ry + rz * rz);
            float tt = sinf((float)(n + 1) * (3.14159265358979323846f / 5.0f) * rn) / rn;
            x = (tt <= 5.0f)
                ? 0.5f * (cosf(3.14159265358979323846f * 0.2f * tt) + 1.0f) : 0.0f;
        }
        g_rbf[i] = __float2half_rn(x);
    }
}

// ---- CSR/misc kernels ----
__global__ void reset_kernel() {
    int i = blockIdx.x * blockDim.x + threadIdx.x;
    if (i == 0) g_sumsq = 0.0;
    int st = gridDim.x * blockDim.x;
    for (int j = i; j < N_NODES; j += st) g_hist[j] = 0;
}
__global__ void hist_sumsq_kernel(const int* __restrict__ idx,
                                  const float* __restrict__ r) {
    int i = blockIdx.x * blockDim.x + threadIdx.x;
    int st = gridDim.x * blockDim.x;
    for (int e = i; e < E_EDGES; e += st) atomicAdd(&g_hist[idx[e]], 1);
    float s = 0.f;
    for (int j = i; j < E_EDGES * 3; j += st) { float x = r[j]; s += x * x; }
    #pragma unroll
    for (int o = 16; o > 0; o >>= 1) s += __shfl_down_sync(0xffffffffu, s, o);
    __shared__ float ws[8];
    if ((threadIdx.x & 31) == 0) ws[threadIdx.x >> 5] = s;
    __syncthreads();
    if (threadIdx.x < 8) {
        float t = ws[threadIdx.x];
        #pragma unroll
        for (int o = 4; o > 0; o >>= 1) t += __shfl_down_sync(0xffu, t, o);
        if (threadIdx.x == 0) atomicAdd(&g_sumsq, (double)t);
    }
}
__global__ void __launch_bounds__(1024) scan_kernel() {
    const int CH = 20;
    __shared__ int wsum[32];
    int t = threadIdx.x, lane = t & 31, w = t >> 5;
    int base = t * CH;
    int h[CH];
    int s = 0;
    #pragma unroll
    for (int i = 0; i < CH; i++) {
        int j = base + i;
        h[i] = (j < N_NODES) ? g_hist[j] : 0;
        s += h[i];
    }
    int ps = s;
    #pragma unroll
    for (int o = 1; o < 32; o <<= 1) {
        int u = __shfl_up_sync(0xffffffffu, ps, o);
        if (lane >= o) ps += u;
    }
    if (lane == 31) wsum[w] = ps;
    __syncthreads();
    if (w == 0) {
        int v = wsum[lane];
        #pragma unroll
        for (int o = 1; o < 32; o <<= 1) {
            int u = __shfl_up_sync(0xffffffffu, v, o);
            if (lane >= o) v += u;
        }
        wsum[lane] = v;
    }
    __syncthreads();
    int run = ps - s + ((w > 0) ? wsum[w - 1] : 0);
    #pragma unroll
    for (int i = 0; i < CH; i++) {
        int j = base + i;
        if (j < N_NODES) { g_off[j] = run; g_cursor[j] = run; run += h[i]; }
    }
    if (t == 1023) g_off[N_NODES] = run;
}
__global__ void fill_kernel(const int* __restrict__ idx) {
    int i = blockIdx.x * blockDim.x + threadIdx.x;
    int st = gridDim.x * blockDim.x;
    for (int e = i; e < E_EDGES; e += st)
        g_elist[atomicAdd(&g_cursor[idx[e]], 1)] = e;
}

// ---- tensor-core GEMM (A fp16 x B fp16 1-term, w-GEMM 2-term) -> g_msg fp16 ----
__global__ void __launch_bounds__(512, 1)
gemm_kernel(const float* __restrict__ s,
            const float* __restrict__ Wphi, const float* __restrict__ bphi,
            const float* __restrict__ Ww, const float* __restrict__ bw)
{
    extern __shared__ char sm[];
    float* bphi_s = (float*)(sm + OFF_BPHI);
    float* bw_s   = (float*)(sm + OFF_BW);

    const int tid  = threadIdx.x;
    const int wid  = tid >> 5;
    const int lane = tid & 31;
    const int mt   = wid >> 1;       // m-tile 0..7
    const int nh   = wid & 1;        // n-half
    const int group = blockIdx.y;
    const int goff  = group * 128;
    const uint32_t smb = smem_u32(sm);

    // ---- one-time weights into smem ----
    {
        __half* B_s = (__half*)(sm + OFF_B);
        __half* Wwh = (__half*)(sm + OFF_WWH);
        __half* Wwl = (__half*)(sm + OFF_WWL);
        for (int i = tid; i < 128 * 128; i += 512) {
            int n = i >> 7, k = i & 127;
            B_s[n * PITCH + k] = __float2half_rn(Wphi[k * 384 + goff + n]);
        }
        for (int i = tid; i < 128 * 32; i += 512) {
            int n = i >> 5, k = i & 31;
            float x = (k < N_RBF) ? Ww[k * 384 + goff + n] : 0.f;
            __half h, l;
            split1h(x, h, l);
            Wwh[n * WPITCH + k] = h;
            Wwl[n * WPITCH + k] = l;
        }
        if (tid < 128) { bphi_s[tid] = bphi[goff + tid]; bw_s[tid] = bw[goff + tid]; }
    }

    // ldmatrix per-thread address components
    const int arow = mt * 16 + (lane & 15);
    const int acol = (lane >> 4) << 3;
    const int brl  = ((lane >> 4) << 3) + (lane & 7);
    const int bk   = ((lane >> 3) & 1) << 3;

    const uint32_t aOff = (uint32_t)(arow * PITCH + acol) * 2;
    const uint32_t rOff = (uint32_t)(arow * WPITCH + acol) * 2;
    const uint32_t bB = smb + OFF_B   + (uint32_t)((nh * 64 + brl) * PITCH + bk) * 2;
    const uint32_t wH = smb + OFF_WWH + (uint32_t)((nh * 64 + brl) * WPITCH + bk) * 2;
    const uint32_t wL = smb + OFF_WWL + (uint32_t)((nh * 64 + brl) * WPITCH + bk) * 2;

    const int eL   = tid >> 2;          // staging: edge row
    const int cbL  = (tid & 3) * 32;    // staging: col base
    const int rrow = tid >> 2;
    const int rseg = tid & 3;
    const int ep0  = mt * 16 + (lane >> 2);
    const int ep1  = ep0 + 8;
    const int t4   = lane & 3;

    // ---- prologue: prefetch tile 0, stage into buffer 0 ----
    float4 st4[8];
    uint4  rhv;
    {
        const int eb0 = blockIdx.x * TILE_E;
        const float* p = &s[(size_t)(eb0 + eL) * 128 + cbL];
        #pragma unroll
        for (int q = 0; q < 8; q++) st4[q] = __ldg((const float4*)p + q);
        rhv = __ldg((const uint4*)&g_rbf[(size_t)(eb0 + rrow) * 32] + rseg);
    }
    {
        __half* A0 = (__half*)(sm + OFF_A0);
        #pragma unroll
        for (int b = 0; b < 8; b++) {
            __half2 h01 = __floats2half2_rn(st4[b].x, st4[b].y);
            __half2 h23 = __floats2half2_rn(st4[b].z, st4[b].w);
            uint2 u;
            u.x = *reinterpret_cast<uint32_t*>(&h01);
            u.y = *reinterpret_cast<uint32_t*>(&h23);
            *(uint2*)&A0[eL * PITCH + cbL + b * 4] = u;
        }
        __half* R0 = (__half*)(sm + OFF_RB0);
        *(uint4*)&R0[rrow * WPITCH + rseg * 8] = rhv;
    }
    __syncthreads();

    uint32_t par = 0;
    for (int tile = blockIdx.x; tile < NTILES; tile += gridDim.x) {
        const int ebase = tile * TILE_E;
        const uint32_t aCur = smb + (par ? OFF_A1 : OFF_A0) + aOff;
        const uint32_t rCur = smb + (par ? OFF_RB1 : OFF_RB0) + rOff;

        // ---- prefetch next tile ----
        {
            int nt = tile + gridDim.x; if (nt >= NTILES) nt = tile;
            const int ebn = nt * TILE_E;
            const float* p = &s[(size_t)(ebn + eL) * 128 + cbL];
            #pragma unroll
            for (int q = 0; q < 8; q++) st4[q] = __ldg((const float4*)p + q);
            rhv = __ldg((const uint4*)&g_rbf[(size_t)(ebn + rrow) * 32] + rseg);
        }

        // ---- w-GEMM: acc_w = rbf(fp16) @ (Wwh + Wwl), K=32 ----
        float acc_w[8][4];
        #pragma unroll
        for (int j = 0; j < 8; j++)
            acc_w[j][0] = acc_w[j][1] = acc_w[j][2] = acc_w[j][3] = 0.f;
        #pragma unroll
        for (int kk = 0; kk < 2; kk++) {
            const uint32_t ko = kk * 32;
            uint32_t a0, a1, a2, a3;
            ldsm4(a0, a1, a2, a3, rCur + ko);
            #pragma unroll
            for (int jj = 0; jj < 4; jj++) {
                const uint32_t bo = (uint32_t)(jj * 16 * WPITCH) * 2 + ko;
                uint32_t h0, h1, h2, h3, l0, l1, l2, l3;
                ldsm4(h0, h1, h2, h3, wH + bo);
                ldsm4(l0, l1, l2, l3, wL + bo);
                mma_f16(acc_w[2*jj],   a0, a1, a2, a3, h0, h1);
                mma_f16(acc_w[2*jj],   a0, a1, a2, a3, l0, l1);
                mma_f16(acc_w[2*jj+1], a0, a1, a2, a3, h2, h3);
                mma_f16(acc_w[2*jj+1], a0, a1, a2, a3, l2, l3);
            }
        }

        // ---- main GEMM: acc = s(fp16) @ B(fp16), K=128, 1-term ----
        float acc[8][4];
        #pragma unroll
        for (int j = 0; j < 8; j++)
            acc[j][0] = acc[j][1] = acc[j][2] = acc[j][3] = 0.f;
        #pragma unroll 1
        for (int kk = 0; kk < 8; kk++) {
            const uint32_t ko = kk * 32;
            uint32_t a0, a1, a2, a3;
            ldsm4(a0, a1, a2, a3, aCur + ko);
            #pragma unroll
            for (int jj = 0; jj < 4; jj++) {
                const uint32_t bo = (uint32_t)(jj * 16 * PITCH) * 2 + ko;
                uint32_t h0, h1, h2, h3;
                ldsm4(h0, h1, h2, h3, bB + bo);
                mma_f16(acc[2*jj],   a0, a1, a2, a3, h0, h1);
                mma_f16(acc[2*jj+1], a0, a1, a2, a3, h2, h3);
            }
        }

        // ---- epilogue: sp = (acc_w + bw) * (acc + bphi) -> fp16 STG.32 ----
        {
            __half* row0 = &g_msg[(size_t)(ebase + ep0) * 384 + goff];
            __half* row1 = &g_msg[(size_t)(ebase + ep1) * 384 + goff];
            #pragma unroll
            for (int j = 0; j < 8; j++) {
                int cj = nh * 64 + j * 8 + t4 * 2;
                ull bp  = *(ull*)&bphi_s[cj];
                ull bwj = *(ull*)&bw_s[cj];
                ull w0 = add2(pack2(acc_w[j][0], acc_w[j][1]), bwj);
                ull w1 = add2(pack2(acc_w[j][2], acc_w[j][3]), bwj);
                float2 p0 = unpack2(mul2(w0, add2(pack2(acc[j][0], acc[j][1]), bp)));
                float2 p1 = unpack2(mul2(w1, add2(pack2(acc[j][2], acc[j][3]), bp)));
                __half2 q0 = __floats2half2_rn(p0.x, p0.y);
                __half2 q1 = __floats2half2_rn(p1.x, p1.y);
                *(uint32_t*)(row0 + cj) = *reinterpret_cast<uint32_t*>(&q0);
                *(uint32_t*)(row1 + cj) = *reinterpret_cast<uint32_t*>(&q1);
            }
        }

        // ---- stage next tile into the OTHER buffer ----
        {
            __half* An = (__half*)(sm + (par ? OFF_A0 : OFF_A1));
            #pragma unroll
            for (int b = 0; b < 8; b++) {
                __half2 h01 = __floats2half2_rn(st4[b].x, st4[b].y);
                __half2 h23 = __floats2half2_rn(st4[b].z, st4[b].w);
                uint2 u;
                u.x = *reinterpret_cast<uint32_t*>(&h01);
                u.y = *reinterpret_cast<uint32_t*>(&h23);
                *(uint2*)&An[eL * PITCH + cbL + b * 4] = u;
            }
            __half* Rn = (__half*)(sm + (par ? OFF_RB0 : OFF_RB1));
            *(uint4*)&Rn[rrow * WPITCH + rseg * 8] = rhv;
        }
        __syncthreads();
        par ^= 1;
    }
}

// ---- per-node gather (fp16 msg, 4x unroll) ----
__global__ void __launch_bounds__(128)
gather_kernel(const float* __restrict__ r, const float* __restrict__ v,
              float* __restrict__ out)
{
    const int n = blockIdx.x;
    const int f = threadIdx.x;
    const float ginv = (float)(1.0 / sqrt(g_sumsq));
    const int beg = g_off[n], end = g_off[n + 1];

    float a0 = 0.f, a1 = 0.f, a2 = 0.f, as = 0.f;
    int p = beg;
    #pragma unroll 1
    for (; p + 4 <= end; p += 4) {
        int e[4];
        #pragma unroll
        for (int q = 0; q < 4; q++) e[q] = g_elist[p + q];
        #pragma unroll
        for (int q = 0; q < 4; q++) {
            const __half* m  = &g_msg[(size_t)e[q] * 384];
            const float*  vp = &v[(size_t)e[q] * 384];
            float sp0 = __half2float(m[f]);
            float sp1 = __half2float(m[128 + f]);
            float sp2 = __half2float(m[256 + f]);
            float v0 = vp[f], v1 = vp[128 + f], v2 = vp[256 + f];
            float r0 = __ldg(&r[e[q] * 3]);
            float r1 = __ldg(&r[e[q] * 3 + 1]);
            float r2 = __ldg(&r[e[q] * 3 + 2]);
            a0 += sp2 * (r0 * ginv) + sp0 * v0;
            a1 += sp2 * (r1 * ginv) + sp0 * v1;
            a2 += sp2 * (r2 * ginv) + sp0 * v2;
            as += sp1;
        }
    }
    #pragma unroll 1
    for (; p < end; p++) {
        const int e = g_elist[p];
        const __half* m  = &g_msg[(size_t)e * 384];
        const float*  vp = &v[(size_t)e * 384];
        float sp0 = __half2float(m[f]);
        float sp1 = __half2float(m[128 + f]);
        float sp2 = __half2float(m[256 + f]);
        float r0 = __ldg(&r[e * 3]), r1 = __ldg(&r[e * 3 + 1]), r2 = __ldg(&r[e * 3 + 2]);
        a0 += sp2 * (r0 * ginv) + sp0 * vp[f];
        a1 += sp2 * (r1 * ginv) + sp0 * vp[128 + f];
        a2 += sp2 * (r2 * ginv) + sp0 * vp[256 + f];
        as += sp1;
    }
    size_t ob = (size_t)n * 384;
    out[ob + f]       = a0;
    out[ob + 128 + f] = a1;
    out[ob + 256 + f] = a2;
    out[OUT_S_OFF + (size_t)n * 128 + f] = as;
}

extern "C" void kernel_launch(void* const* d_in, const int* in_sizes, int n_in,
                              void* d_out, int out_size) {
    const float* s    = (const float*)d_in[0];
    const float* r    = (const float*)d_in[1];
    const float* v    = (const float*)d_in[2];
    const int*   idx  = (const int*)d_in[3];
    const float* Wphi = (const float*)d_in[4];
    const float* bphi = (const float*)d_in[5];
    const float* Ww   = (const float*)d_in[6];
    const float* bw   = (const float*)d_in[7];
    float* out = (float*)d_out;

    static cudaStream_t s2 = nullptr;
    static cudaEvent_t evFork = nullptr, evJoin = nullptr;
    if (s2 == nullptr) {
        cudaStreamCreateWithFlags(&s2, cudaStreamNonBlocking);
        cudaEventCreateWithFlags(&evFork, cudaEventDisableTiming);
        cudaEventCreateWithFlags(&evJoin, cudaEventDisableTiming);
    }

    cudaEventRecord(evFork, 0);
    cudaStreamWaitEvent(s2, evFork, 0);

    reset_kernel<<<64, 256, 0, s2>>>();
    hist_sumsq_kernel<<<256, 256, 0, s2>>>(idx, r);
    scan_kernel<<<1, 1024, 0, s2>>>();
    fill_kernel<<<256, 256, 0, s2>>>(idx);
    cudaEventRecord(evJoin, s2);

    rbf_kernel<<<2048, 256>>>(r);

    cudaFuncSetAttribute(gemm_kernel,
                         cudaFuncAttributeMaxDynamicSharedMemorySize, SMEM_SZ);
    gemm_kernel<<<dim3(148, 3), 512, SMEM_SZ>>>(s, Wphi, bphi, Ww, bw);

    cudaStreamWaitEvent(0, evJoin, 0);
    gather_kernel<<<N_NODES, 128>>>(r, v, out);
}